// round 2
// baseline (speedup 1.0000x reference)
#include <cuda_runtime.h>
#include <cstddef>
#include <cstdint>

// Problem constants: N=50000, F=128, H=8, HID=8, CLS=40, E=1.6M
#define NMAX 50000
#define EMAX 1700000   // E + self loops head-room

// ---------------- static device scratch ----------------
__device__ float g_hfeat[(size_t)NMAX * 64];
__device__ float g_actA [(size_t)NMAX * 64];
__device__ float g_actB [(size_t)NMAX * 64];
__device__ float g_s    [(size_t)NMAX * 16];   // per-node scores: [0..7]=src, [8..15]=dst
__device__ int   g_col  [EMAX];                // CSR column (src) indices grouped by dst
__device__ int   g_rowptr[NMAX + 1];
__device__ int   g_cursor[NMAX];
__device__ int   g_cnt   [NMAX];
__device__ float g_y    [(size_t)NMAX * 512];  // layer-5 pre-GEMM aggregate [N,8,64]
__device__ float g_Wfold[128 * 16];
__device__ float g_Wp   [512 * 40];
__device__ float g_pre  [(size_t)NMAX * 40];

// ---------------- CSR build ----------------
__global__ void k_init_cnt(int* cnt, int n) {
    int i = blockIdx.x * blockDim.x + threadIdx.x;
    if (i < n) cnt[i] = 1;                       // self loop
}

__global__ void k_hist(const int* __restrict__ dst, int* cnt, int E) {
    int i = blockIdx.x * blockDim.x + threadIdx.x;
    if (i < E) atomicAdd(&cnt[dst[i]], 1);
}

__global__ void k_scan(const int* __restrict__ cnt, int* rowptr, int* cursor, int n) {
    __shared__ int sm[1024];
    __shared__ int carry;
    int tid = threadIdx.x;
    if (tid == 0) carry = 0;
    __syncthreads();
    for (int base = 0; base < n; base += 1024) {
        int i = base + tid;
        int v = (i < n) ? cnt[i] : 0;
        sm[tid] = v;
        __syncthreads();
        for (int off = 1; off < 1024; off <<= 1) {
            int t = (tid >= off) ? sm[tid - off] : 0;
            __syncthreads();
            sm[tid] += t;
            __syncthreads();
        }
        int excl = carry + sm[tid] - v;
        if (i < n) { rowptr[i] = excl; cursor[i] = excl; }
        __syncthreads();
        if (tid == 0) carry += sm[1023];
        __syncthreads();
    }
    if (tid == 0) rowptr[n] = carry;
}

__global__ void k_scatter(const int* __restrict__ ei, int* cursor, int* col, int E, int n) {
    int i = blockIdx.x * blockDim.x + threadIdx.x;
    if (i < E) {
        int s = ei[i];
        int d = ei[E + i];
        int p = atomicAdd(&cursor[d], 1);
        col[p] = s;
    } else if (i < E + n) {
        int nd = i - E;
        int p = atomicAdd(&cursor[nd], 1);
        col[p] = nd;
    }
}

// ---------------- generic SGEMM: C[M,Nc] = A[M,K] @ B[K,Nc] ----------------
__global__ __launch_bounds__(256) void k_gemm(
    const float* __restrict__ A, const float* __restrict__ B, float* __restrict__ C,
    int M, int Nc, int K)
{
    __shared__ float As[16][132];
    __shared__ float Bs[16][64];
    int tid = threadIdx.x;
    int bm = blockIdx.y * 128;
    int bn = blockIdx.x * 64;
    int tx = tid & 15;
    int ty = tid >> 4;
    float acc[8][4];
#pragma unroll
    for (int i = 0; i < 8; i++)
#pragma unroll
        for (int j = 0; j < 4; j++) acc[i][j] = 0.f;

    for (int k0 = 0; k0 < K; k0 += 16) {
#pragma unroll
        for (int it = 0; it < 2; it++) {
            int idx = tid + it * 256;
            int m  = idx >> 2;
            int kq = (idx & 3) * 4;
            int gm = bm + m;
            float4 v = make_float4(0.f, 0.f, 0.f, 0.f);
            if (gm < M) v = *(const float4*)(A + (size_t)gm * K + k0 + kq);
            As[kq + 0][m] = v.x;
            As[kq + 1][m] = v.y;
            As[kq + 2][m] = v.z;
            As[kq + 3][m] = v.w;
        }
#pragma unroll
        for (int it = 0; it < 4; it++) {
            int idx = tid + it * 256;
            int kk = idx >> 6;
            int cc = idx & 63;
            int gc = bn + cc;
            float v = 0.f;
            if (gc < Nc) v = B[(size_t)(k0 + kk) * Nc + gc];
            Bs[kk][cc] = v;
        }
        __syncthreads();
#pragma unroll
        for (int kk = 0; kk < 16; kk++) {
            float4 a0 = *(const float4*)(&As[kk][ty * 8]);
            float4 a1 = *(const float4*)(&As[kk][ty * 8 + 4]);
            float4 b  = *(const float4*)(&Bs[kk][tx * 4]);
            float av[8] = {a0.x, a0.y, a0.z, a0.w, a1.x, a1.y, a1.z, a1.w};
            float bv[4] = {b.x, b.y, b.z, b.w};
#pragma unroll
            for (int i = 0; i < 8; i++)
#pragma unroll
                for (int j = 0; j < 4; j++) acc[i][j] += av[i] * bv[j];
        }
        __syncthreads();
    }
#pragma unroll
    for (int i = 0; i < 8; i++) {
        int gm = bm + ty * 8 + i;
        if (gm >= M) continue;
#pragma unroll
        for (int j = 0; j < 4; j++) {
            int gc = bn + tx * 4 + j;
            if (gc < Nc) C[(size_t)gm * Nc + gc] = acc[i][j];
        }
    }
}

// ---------------- attention-matrix fold ----------------
__global__ void k_fold(const float* __restrict__ W, const float* __restrict__ a_src,
                       const float* __restrict__ a_dst, float* __restrict__ Wf,
                       int K, int C)
{
    int idx = blockIdx.x * blockDim.x + threadIdx.x;
    if (idx >= K * 16) return;
    int k = idx >> 4;
    int j = idx & 15;
    int h = j & 7;
    const float* a = (j < 8) ? a_src : a_dst;
    float sum = 0.f;
    for (int c = 0; c < C; c++)
        sum += W[(size_t)k * 8 * C + h * C + c] * a[h * C + c];
    Wf[idx] = sum;
}

__global__ void k_wprime(const float* __restrict__ W5, float* __restrict__ Wp) {
    int idx = blockIdx.x * blockDim.x + threadIdx.x;
    if (idx >= 512 * 40) return;
    int kk = idx / 40;
    int c  = idx % 40;
    int h  = kk >> 6;
    int k  = kk & 63;
    Wp[idx] = W5[(size_t)k * 320 + h * 40 + c];
}

// ---------------- softmax stats (pass 1): per-node m[8], inv[8] ----------------
__device__ __forceinline__ void softmax_stats(
    const float* __restrict__ s, const int* __restrict__ colx,
    int node, int lane, int beg, int end,
    float* __restrict__ m, float* __restrict__ inv, float* __restrict__ sdv)
{
    const float* sd = s + (size_t)node * 16 + 8;
#pragma unroll
    for (int h = 0; h < 8; h++) sdv[h] = __ldg(sd + h);

    float l[8];
#pragma unroll
    for (int h = 0; h < 8; h++) { m[h] = -1e30f; l[h] = 0.f; }

    for (int e = beg + lane; e < end; e += 32) {
        int si = colx[e];
        const float4* sp = (const float4*)(s + (size_t)si * 16);
        float4 s0 = __ldg(sp);
        float4 s1 = __ldg(sp + 1);
        float ss[8] = {s0.x, s0.y, s0.z, s0.w, s1.x, s1.y, s1.z, s1.w};
#pragma unroll
        for (int h = 0; h < 8; h++) {
            float al = ss[h] + sdv[h];
            al = al > 0.f ? al : 0.2f * al;
            if (al > m[h]) { l[h] = l[h] * __expf(m[h] - al) + 1.f; m[h] = al; }
            else            l[h] += __expf(al - m[h]);
        }
    }
#pragma unroll
    for (int off = 16; off; off >>= 1) {
#pragma unroll
        for (int h = 0; h < 8; h++) {
            float om = __shfl_xor_sync(0xffffffffu, m[h], off);
            float ol = __shfl_xor_sync(0xffffffffu, l[h], off);
            float nm = fmaxf(m[h], om);
            l[h] = l[h] * __expf(m[h] - nm) + ol * __expf(om - nm);
            m[h] = nm;
        }
    }
#pragma unroll
    for (int h = 0; h < 8; h++) inv[h] = 1.f / (l[h] + 1e-16f);
}

// ---------------- concat-layer aggregation (layers 1-4), edge-parallel ----------
// 2 lanes per edge (p = lane&1 picks 32 channels = 4 heads), 16 edges in flight.
__global__ __launch_bounds__(256) void k_agg_cat(
    const float* __restrict__ hfeat, const float* __restrict__ s,
    const int* __restrict__ rowptr, const int* __restrict__ colx,
    const float* __restrict__ bias, float* __restrict__ out, int n)
{
    int node = (blockIdx.x * blockDim.x + threadIdx.x) >> 5;
    if (node >= n) return;
    int lane = threadIdx.x & 31;
    int beg = rowptr[node], end = rowptr[node + 1];

    float m[8], inv[8], sdv[8];
    softmax_stats(s, colx, node, lane, beg, end, m, inv, sdv);

    int p = lane & 1;        // half selector: channels [p*32, p*32+32), heads p*4..p*4+3
    int g = lane >> 1;       // edge stride index (16 concurrent edges)

    float m4[4], inv4[4], sdv4[4];
#pragma unroll
    for (int hh = 0; hh < 4; hh++) {
        m4[hh]   = m[p * 4 + hh];
        inv4[hh] = inv[p * 4 + hh];
        sdv4[hh] = sdv[p * 4 + hh];
    }

    float acc[32];
#pragma unroll
    for (int i = 0; i < 32; i++) acc[i] = 0.f;

    for (int e = beg + g; e < end; e += 16) {
        int si = colx[e];
        float4 sv = __ldg((const float4*)(s + (size_t)si * 16) + p);
        float ssv[4] = {sv.x, sv.y, sv.z, sv.w};
        float al[4];
#pragma unroll
        for (int hh = 0; hh < 4; hh++) {
            float a = ssv[hh] + sdv4[hh];
            a = a > 0.f ? a : 0.2f * a;
            al[hh] = __expf(a - m4[hh]) * inv4[hh];
        }
        const float4* hv = (const float4*)(hfeat + (size_t)si * 64 + p * 32);
#pragma unroll
        for (int c4 = 0; c4 < 8; c4++) {
            float4 v = __ldg(hv + c4);
            float a = al[c4 >> 1];
            acc[c4 * 4 + 0] += a * v.x;
            acc[c4 * 4 + 1] += a * v.y;
            acc[c4 * 4 + 2] += a * v.z;
            acc[c4 * 4 + 3] += a * v.w;
        }
    }

    // reduce across g (lanes sharing p differ in bits 1..4)
#pragma unroll
    for (int off = 2; off <= 16; off <<= 1)
#pragma unroll
        for (int i = 0; i < 32; i++)
            acc[i] += __shfl_xor_sync(0xffffffffu, acc[i], off);

    // lane (p,g) writes channels p*32 + g*2 .. +1
    int c  = g * 2;
    int ch = p * 32 + c;
    float r0 = acc[c]     + __ldg(bias + ch);
    float r1 = acc[c + 1] + __ldg(bias + ch + 1);
    r0 = r0 > 0.f ? r0 : 0.2f * r0;
    r1 = r1 > 0.f ? r1 : 0.2f * r1;
    size_t o = (size_t)node * 64 + ch;
    out[o]     = r0;
    out[o + 1] = r1;
}

// ---------------- layer-5 aggregation: y[N,8,64], edge-parallel ----------------
// 8 lanes per edge (q = lane&7 picks 8 channels, all 8 heads), 4 edges in flight.
__global__ __launch_bounds__(256) void k_agg_mean(
    const float* __restrict__ xin, const float* __restrict__ s,
    const int* __restrict__ rowptr, const int* __restrict__ colx,
    float* __restrict__ y, int n)
{
    int node = (blockIdx.x * blockDim.x + threadIdx.x) >> 5;
    if (node >= n) return;
    int lane = threadIdx.x & 31;
    int beg = rowptr[node], end = rowptr[node + 1];

    float m[8], inv[8], sdv[8];
    softmax_stats(s, colx, node, lane, beg, end, m, inv, sdv);

    int q = lane & 7;        // channel octet: [q*8, q*8+8)
    int g = lane >> 3;       // edge stride index (4 concurrent edges)

    float acc[64];           // acc[h*8 + j]
#pragma unroll
    for (int i = 0; i < 64; i++) acc[i] = 0.f;

    for (int e = beg + g; e < end; e += 4) {
        int si = colx[e];
        const float4* sp = (const float4*)(s + (size_t)si * 16);
        float4 s0 = __ldg(sp);
        float4 s1 = __ldg(sp + 1);
        float ss[8] = {s0.x, s0.y, s0.z, s0.w, s1.x, s1.y, s1.z, s1.w};
        float al[8];
#pragma unroll
        for (int h = 0; h < 8; h++) {
            float a = ss[h] + sdv[h];
            a = a > 0.f ? a : 0.2f * a;
            al[h] = __expf(a - m[h]) * inv[h];
        }
        const float4* vp = (const float4*)(xin + (size_t)si * 64 + q * 8);
        float4 v0 = __ldg(vp);
        float4 v1 = __ldg(vp + 1);
        float vv[8] = {v0.x, v0.y, v0.z, v0.w, v1.x, v1.y, v1.z, v1.w};
#pragma unroll
        for (int h = 0; h < 8; h++)
#pragma unroll
            for (int j = 0; j < 8; j++)
                acc[h * 8 + j] += al[h] * vv[j];
    }

    // reduce across g (lanes sharing q differ in bits 3,4)
#pragma unroll
    for (int off = 8; off <= 16; off <<= 1)
#pragma unroll
        for (int i = 0; i < 64; i++)
            acc[i] += __shfl_xor_sync(0xffffffffu, acc[i], off);

    // lanes g=0..3 all hold full sums; lane (g,q) writes heads g and g+4
#pragma unroll
    for (int t = 0; t < 2; t++) {
        int h = g + t * 4;
        size_t o = (size_t)node * 512 + (size_t)h * 64 + q * 8;
        float4 w0 = make_float4(acc[h * 8 + 0], acc[h * 8 + 1], acc[h * 8 + 2], acc[h * 8 + 3]);
        float4 w1 = make_float4(acc[h * 8 + 4], acc[h * 8 + 5], acc[h * 8 + 6], acc[h * 8 + 7]);
        *(float4*)(y + o)     = w0;
        *(float4*)(y + o + 4) = w1;
    }
}

// ---------------- final: mean(/8) + b5 + log_softmax ----------------
__global__ __launch_bounds__(256) void k_lsm(
    const float* __restrict__ pre, const float* __restrict__ b5,
    float* __restrict__ out, int n)
{
    int node = (blockIdx.x * blockDim.x + threadIdx.x) >> 5;
    if (node >= n) return;
    int lane = threadIdx.x & 31;
    float v0 = pre[(size_t)node * 40 + lane] * 0.125f + __ldg(b5 + lane);
    float v1 = -1e30f;
    if (lane < 8) v1 = pre[(size_t)node * 40 + 32 + lane] * 0.125f + __ldg(b5 + 32 + lane);
    float mx = fmaxf(v0, v1);
#pragma unroll
    for (int off = 16; off; off >>= 1) mx = fmaxf(mx, __shfl_xor_sync(0xffffffffu, mx, off));
    float sum = __expf(v0 - mx) + (lane < 8 ? __expf(v1 - mx) : 0.f);
#pragma unroll
    for (int off = 16; off; off >>= 1) sum += __shfl_xor_sync(0xffffffffu, sum, off);
    float lse = mx + __logf(sum);
    out[(size_t)node * 40 + lane] = v0 - lse;
    if (lane < 8) out[(size_t)node * 40 + 32 + lane] = v1 - lse;
}

// ---------------- host ----------------
static void* sym(const void* s) {
    void* p = nullptr;
    cudaGetSymbolAddress(&p, s);
    return p;
}

extern "C" void kernel_launch(void* const* d_in, const int* in_sizes, int n_in,
                              void* d_out, int out_size)
{
    const float* x   = (const float*)d_in[0];
    const int*   ei  = (const int*)d_in[1];
    const float* Ws[5]  = {(const float*)d_in[2],  (const float*)d_in[6],
                           (const float*)d_in[10], (const float*)d_in[14],
                           (const float*)d_in[18]};
    const float* asv[5] = {(const float*)d_in[3],  (const float*)d_in[7],
                           (const float*)d_in[11], (const float*)d_in[15],
                           (const float*)d_in[19]};
    const float* adv[5] = {(const float*)d_in[4],  (const float*)d_in[8],
                           (const float*)d_in[12], (const float*)d_in[16],
                           (const float*)d_in[20]};
    const float* bs[5]  = {(const float*)d_in[5],  (const float*)d_in[9],
                           (const float*)d_in[13], (const float*)d_in[17],
                           (const float*)d_in[21]};

    int n = in_sizes[0] / 128;
    int E = in_sizes[1] / 2;

    float* hfeat  = (float*)sym(g_hfeat);
    float* actA   = (float*)sym(g_actA);
    float* actB   = (float*)sym(g_actB);
    float* sbuf   = (float*)sym(g_s);
    int*   col    = (int*)  sym(g_col);
    int*   rowptr = (int*)  sym(g_rowptr);
    int*   cursor = (int*)  sym(g_cursor);
    int*   cnt    = (int*)  sym(g_cnt);
    float* ybuf   = (float*)sym(g_y);
    float* Wfold  = (float*)sym(g_Wfold);
    float* Wp     = (float*)sym(g_Wp);
    float* pre    = (float*)sym(g_pre);

    // ---- CSR build (dst-grouped) ----
    k_init_cnt<<<(n + 255) / 256, 256>>>(cnt, n);
    k_hist<<<(E + 255) / 256, 256>>>(ei + E, cnt, E);
    k_scan<<<1, 1024>>>(cnt, rowptr, cursor, n);
    k_scatter<<<(E + n + 255) / 256, 256>>>(ei, cursor, col, E, n);

    int warpBlocks = (n + 7) / 8;

    // ---- layers 1..4 (concat, lrelu) ----
    const float* cur = x;
    int K = 128;
    float* acts[2] = {actA, actB};
    for (int L = 0; L < 4; L++) {
        k_fold<<<(K * 16 + 255) / 256, 256>>>(Ws[L], asv[L], adv[L], Wfold, K, 8);
        {
            dim3 g(1, (n + 127) / 128);
            k_gemm<<<g, 256>>>(cur, Wfold, sbuf, n, 16, K);
        }
        {
            dim3 g(1, (n + 127) / 128);
            k_gemm<<<g, 256>>>(cur, Ws[L], hfeat, n, 64, K);
        }
        k_agg_cat<<<warpBlocks, 256>>>(hfeat, sbuf, rowptr, col, bs[L],
                                       acts[L & 1], n);
        cur = acts[L & 1];
        K = 64;
    }

    // ---- layer 5: aggregate x4 per head, then block-diag GEMM ----
    k_fold<<<(64 * 16 + 255) / 256, 256>>>(Ws[4], asv[4], adv[4], Wfold, 64, 40);
    {
        dim3 g(1, (n + 127) / 128);
        k_gemm<<<g, 256>>>(cur, Wfold, sbuf, n, 16, 64);
    }
    k_agg_mean<<<warpBlocks, 256>>>(cur, sbuf, rowptr, col, ybuf, n);
    k_wprime<<<(512 * 40 + 255) / 256, 256>>>(Ws[4], Wp);
    {
        dim3 g(1, (n + 127) / 128);
        k_gemm<<<g, 256>>>(ybuf, Wp, pre, n, 40, 512);
    }
    k_lsm<<<warpBlocks, 256>>>(pre, bs[4], (float*)d_out, n);
}

// round 3
// speedup vs baseline: 1.7021x; 1.7021x over previous
#include <cuda_runtime.h>
#include <cstddef>
#include <cstdint>

// Problem constants: N=50000, F=128, H=8, HID=8, CLS=40, E=1.6M
#define NMAX 50000
#define EMAX 1700000   // E + self loops head-room

// ---------------- static device scratch ----------------
__device__ float g_hfeat[(size_t)NMAX * 64];
__device__ float g_actA [(size_t)NMAX * 64];
__device__ float g_actB [(size_t)NMAX * 64];
__device__ float g_s    [(size_t)NMAX * 16];   // per-node scores: [0..7]=src, [8..15]=dst
__device__ float g_alpha[(size_t)EMAX * 8];    // per-edge per-head attention weights
__device__ int   g_col  [EMAX];                // CSR column (src) indices grouped by dst
__device__ int   g_rowptr[NMAX + 1];
__device__ int   g_cursor[NMAX];
__device__ int   g_cnt   [NMAX];
__device__ float g_y    [(size_t)NMAX * 512];  // layer-5 pre-GEMM aggregate [N,8,64]
__device__ float g_Wfold[128 * 16];
__device__ float g_Wp   [512 * 40];
__device__ float g_pre  [(size_t)NMAX * 40];

// ---------------- CSR build ----------------
__global__ void k_init_cnt(int* cnt, int n) {
    int i = blockIdx.x * blockDim.x + threadIdx.x;
    if (i < n) cnt[i] = 1;                       // self loop
}

__global__ void k_hist(const int* __restrict__ dst, int* cnt, int E) {
    int i = blockIdx.x * blockDim.x + threadIdx.x;
    if (i < E) atomicAdd(&cnt[dst[i]], 1);
}

__global__ void k_scan(const int* __restrict__ cnt, int* rowptr, int* cursor, int n) {
    __shared__ int sm[1024];
    __shared__ int carry;
    int tid = threadIdx.x;
    if (tid == 0) carry = 0;
    __syncthreads();
    for (int base = 0; base < n; base += 1024) {
        int i = base + tid;
        int v = (i < n) ? cnt[i] : 0;
        sm[tid] = v;
        __syncthreads();
        for (int off = 1; off < 1024; off <<= 1) {
            int t = (tid >= off) ? sm[tid - off] : 0;
            __syncthreads();
            sm[tid] += t;
            __syncthreads();
        }
        int excl = carry + sm[tid] - v;
        if (i < n) { rowptr[i] = excl; cursor[i] = excl; }
        __syncthreads();
        if (tid == 0) carry += sm[1023];
        __syncthreads();
    }
    if (tid == 0) rowptr[n] = carry;
}

__global__ void k_scatter(const int* __restrict__ ei, int* cursor, int* col, int E, int n) {
    int i = blockIdx.x * blockDim.x + threadIdx.x;
    if (i < E) {
        int s = ei[i];
        int d = ei[E + i];
        int p = atomicAdd(&cursor[d], 1);
        col[p] = s;
    } else if (i < E + n) {
        int nd = i - E;
        int p = atomicAdd(&cursor[nd], 1);
        col[p] = nd;
    }
}

// ---------------- SGEMM: C[M,Nc] = A[M,K] @ B[K,Nc] ----------------
// BM=128, BN=16*TN, BK=16, 256 threads, microtile 8 x TN.
template<int TN>
__global__ __launch_bounds__(256) void k_gemm(
    const float* __restrict__ A, const float* __restrict__ B, float* __restrict__ C,
    int M, int Nc, int K)
{
    const int BN = 16 * TN;
    __shared__ float As[16][132];
    __shared__ float Bs[16][BN];
    int tid = threadIdx.x;
    int bm = blockIdx.y * 128;
    int bn = blockIdx.x * BN;
    int tx = tid & 15;
    int ty = tid >> 4;
    float acc[8][TN];
#pragma unroll
    for (int i = 0; i < 8; i++)
#pragma unroll
        for (int j = 0; j < TN; j++) acc[i][j] = 0.f;

    for (int k0 = 0; k0 < K; k0 += 16) {
        // A tile (128x16) as 512 float4s, 2 per thread
#pragma unroll
        for (int it = 0; it < 2; it++) {
            int idx = tid + it * 256;
            int m  = idx >> 2;
            int kq = (idx & 3) * 4;
            int gm = bm + m;
            float4 v = make_float4(0.f, 0.f, 0.f, 0.f);
            if (gm < M) v = *(const float4*)(A + (size_t)gm * K + k0 + kq);
            As[kq + 0][m] = v.x;
            As[kq + 1][m] = v.y;
            As[kq + 2][m] = v.z;
            As[kq + 3][m] = v.w;
        }
        // B tile (16 x BN)
        for (int idx = tid; idx < 16 * BN; idx += 256) {
            int kk = idx / BN;
            int cc = idx % BN;
            int gc = bn + cc;
            float v = 0.f;
            if (gc < Nc) v = B[(size_t)(k0 + kk) * Nc + gc];
            Bs[kk][cc] = v;
        }
        __syncthreads();
#pragma unroll
        for (int kk = 0; kk < 16; kk++) {
            float4 a0 = *(const float4*)(&As[kk][ty * 8]);
            float4 a1 = *(const float4*)(&As[kk][ty * 8 + 4]);
            float av[8] = {a0.x, a0.y, a0.z, a0.w, a1.x, a1.y, a1.z, a1.w};
            float bv[TN];
#pragma unroll
            for (int j = 0; j < TN; j++) bv[j] = Bs[kk][tx * TN + j];
#pragma unroll
            for (int i = 0; i < 8; i++)
#pragma unroll
                for (int j = 0; j < TN; j++) acc[i][j] += av[i] * bv[j];
        }
        __syncthreads();
    }
#pragma unroll
    for (int i = 0; i < 8; i++) {
        int gm = bm + ty * 8 + i;
        if (gm >= M) continue;
#pragma unroll
        for (int j = 0; j < TN; j++) {
            int gc = bn + tx * TN + j;
            if (gc < Nc) C[(size_t)gm * Nc + gc] = acc[i][j];
        }
    }
}

// ---------------- attention-matrix fold ----------------
__global__ void k_fold(const float* __restrict__ W, const float* __restrict__ a_src,
                       const float* __restrict__ a_dst, float* __restrict__ Wf,
                       int K, int C)
{
    int idx = blockIdx.x * blockDim.x + threadIdx.x;
    if (idx >= K * 16) return;
    int k = idx >> 4;
    int j = idx & 15;
    int h = j & 7;
    const float* a = (j < 8) ? a_src : a_dst;
    float sum = 0.f;
    for (int c = 0; c < C; c++)
        sum += W[(size_t)k * 8 * C + h * C + c] * a[h * C + c];
    Wf[idx] = sum;
}

__global__ void k_wprime(const float* __restrict__ W5, float* __restrict__ Wp) {
    int idx = blockIdx.x * blockDim.x + threadIdx.x;
    if (idx >= 512 * 40) return;
    int kk = idx / 40;
    int c  = idx % 40;
    int h  = kk >> 6;
    int k  = kk & 63;
    Wp[idx] = W5[(size_t)k * 320 + h * 40 + c];
}

// ---------------- softmax stats + alpha write (one warp per node) ----------------
__device__ __forceinline__ void softmax_alpha(
    const float* __restrict__ s, const int* __restrict__ colx,
    float* __restrict__ alpha, int node, int lane, int beg, int end)
{
    float sdv[8];
    const float* sd = s + (size_t)node * 16 + 8;
#pragma unroll
    for (int h = 0; h < 8; h++) sdv[h] = __ldg(sd + h);

    float m[8], l[8];
#pragma unroll
    for (int h = 0; h < 8; h++) { m[h] = -1e30f; l[h] = 0.f; }

    for (int e = beg + lane; e < end; e += 32) {
        int si = colx[e];
        const float4* sp = (const float4*)(s + (size_t)si * 16);
        float4 s0 = __ldg(sp);
        float4 s1 = __ldg(sp + 1);
        float ss[8] = {s0.x, s0.y, s0.z, s0.w, s1.x, s1.y, s1.z, s1.w};
#pragma unroll
        for (int h = 0; h < 8; h++) {
            float al = ss[h] + sdv[h];
            al = al > 0.f ? al : 0.2f * al;
            if (al > m[h]) { l[h] = l[h] * __expf(m[h] - al) + 1.f; m[h] = al; }
            else            l[h] += __expf(al - m[h]);
        }
    }
#pragma unroll
    for (int off = 16; off; off >>= 1) {
#pragma unroll
        for (int h = 0; h < 8; h++) {
            float om = __shfl_xor_sync(0xffffffffu, m[h], off);
            float ol = __shfl_xor_sync(0xffffffffu, l[h], off);
            float nm = fmaxf(m[h], om);
            l[h] = l[h] * __expf(m[h] - nm) + ol * __expf(om - nm);
            m[h] = nm;
        }
    }
    float inv[8];
#pragma unroll
    for (int h = 0; h < 8; h++) inv[h] = 1.f / (l[h] + 1e-16f);

    for (int e = beg + lane; e < end; e += 32) {
        int si = colx[e];
        const float4* sp = (const float4*)(s + (size_t)si * 16);
        float4 s0 = __ldg(sp);
        float4 s1 = __ldg(sp + 1);
        float ss[8] = {s0.x, s0.y, s0.z, s0.w, s1.x, s1.y, s1.z, s1.w};
        float av[8];
#pragma unroll
        for (int h = 0; h < 8; h++) {
            float al = ss[h] + sdv[h];
            al = al > 0.f ? al : 0.2f * al;
            av[h] = __expf(al - m[h]) * inv[h];
        }
        float4* ap = (float4*)(alpha + (size_t)e * 8);
        ap[0] = make_float4(av[0], av[1], av[2], av[3]);
        ap[1] = make_float4(av[4], av[5], av[6], av[7]);
    }
    __syncwarp();
}

// ---------------- concat-layer aggregation (layers 1-4) ----------------
// lane -> (head h, channel pair cb); phase 3 unrolled x4 for gather MLP.
__global__ __launch_bounds__(256) void k_agg_cat(
    const float* __restrict__ hfeat, const float* __restrict__ s,
    const int* __restrict__ rowptr, const int* __restrict__ colx,
    const float* __restrict__ bias, float* __restrict__ out,
    float* __restrict__ alpha, int n)
{
    int node = (blockIdx.x * blockDim.x + threadIdx.x) >> 5;
    if (node >= n) return;
    int lane = threadIdx.x & 31;
    int beg = rowptr[node], end = rowptr[node + 1];

    softmax_alpha(s, colx, alpha, node, lane, beg, end);

    int h  = lane >> 2;
    int cb = (lane & 3) * 2;
    float a0 = 0.f, a1 = 0.f;

    int e = beg;
    for (; e + 4 <= end; e += 4) {
        int si[4];
        float al[4];
        float2 v[4];
#pragma unroll
        for (int u = 0; u < 4; u++) si[u] = colx[e + u];
#pragma unroll
        for (int u = 0; u < 4; u++) al[u] = __ldg(alpha + (size_t)(e + u) * 8 + h);
#pragma unroll
        for (int u = 0; u < 4; u++)
            v[u] = *(const float2*)(hfeat + (size_t)si[u] * 64 + h * 8 + cb);
#pragma unroll
        for (int u = 0; u < 4; u++) {
            a0 += al[u] * v[u].x;
            a1 += al[u] * v[u].y;
        }
    }
    for (; e < end; e++) {
        int si = colx[e];
        float al = __ldg(alpha + (size_t)e * 8 + h);
        float2 v = *(const float2*)(hfeat + (size_t)si * 64 + h * 8 + cb);
        a0 += al * v.x;
        a1 += al * v.y;
    }

    float r0 = a0 + __ldg(bias + h * 8 + cb);
    float r1 = a1 + __ldg(bias + h * 8 + cb + 1);
    r0 = r0 > 0.f ? r0 : 0.2f * r0;
    r1 = r1 > 0.f ? r1 : 0.2f * r1;
    size_t o = (size_t)node * 64 + h * 8 + cb;
    out[o]     = r0;
    out[o + 1] = r1;
}

// ---------------- layer-5 aggregation: y[N,8,64] ----------------
// lane -> channel pair kb; phase 3 unrolled x2.
__global__ __launch_bounds__(256) void k_agg_mean(
    const float* __restrict__ xin, const float* __restrict__ s,
    const int* __restrict__ rowptr, const int* __restrict__ colx,
    float* __restrict__ y, float* __restrict__ alpha, int n)
{
    int node = (blockIdx.x * blockDim.x + threadIdx.x) >> 5;
    if (node >= n) return;
    int lane = threadIdx.x & 31;
    int beg = rowptr[node], end = rowptr[node + 1];

    softmax_alpha(s, colx, alpha, node, lane, beg, end);

    int kb = lane * 2;
    float acc[8][2];
#pragma unroll
    for (int h = 0; h < 8; h++) { acc[h][0] = 0.f; acc[h][1] = 0.f; }

    int e = beg;
    for (; e + 2 <= end; e += 2) {
        int si0 = colx[e], si1 = colx[e + 1];
        const float4* ap0 = (const float4*)(alpha + (size_t)e * 8);
        const float4* ap1 = (const float4*)(alpha + (size_t)(e + 1) * 8);
        float4 q00 = __ldg(ap0), q01 = __ldg(ap0 + 1);
        float4 q10 = __ldg(ap1), q11 = __ldg(ap1 + 1);
        float2 v0 = *(const float2*)(xin + (size_t)si0 * 64 + kb);
        float2 v1 = *(const float2*)(xin + (size_t)si1 * 64 + kb);
        float a0[8] = {q00.x, q00.y, q00.z, q00.w, q01.x, q01.y, q01.z, q01.w};
        float a1[8] = {q10.x, q10.y, q10.z, q10.w, q11.x, q11.y, q11.z, q11.w};
#pragma unroll
        for (int h = 0; h < 8; h++) {
            acc[h][0] += a0[h] * v0.x + a1[h] * v1.x;
            acc[h][1] += a0[h] * v0.y + a1[h] * v1.y;
        }
    }
    for (; e < end; e++) {
        int si = colx[e];
        const float4* ap = (const float4*)(alpha + (size_t)e * 8);
        float4 q0 = __ldg(ap), q1 = __ldg(ap + 1);
        float2 v = *(const float2*)(xin + (size_t)si * 64 + kb);
        float av[8] = {q0.x, q0.y, q0.z, q0.w, q1.x, q1.y, q1.z, q1.w};
#pragma unroll
        for (int h = 0; h < 8; h++) {
            acc[h][0] += av[h] * v.x;
            acc[h][1] += av[h] * v.y;
        }
    }
#pragma unroll
    for (int h = 0; h < 8; h++) {
        size_t o = (size_t)node * 512 + h * 64 + kb;
        y[o]     = acc[h][0];
        y[o + 1] = acc[h][1];
    }
}

// ---------------- final: mean(/8) + b5 + log_softmax ----------------
__global__ __launch_bounds__(256) void k_lsm(
    const float* __restrict__ pre, const float* __restrict__ b5,
    float* __restrict__ out, int n)
{
    int node = (blockIdx.x * blockDim.x + threadIdx.x) >> 5;
    if (node >= n) return;
    int lane = threadIdx.x & 31;
    float v0 = pre[(size_t)node * 40 + lane] * 0.125f + __ldg(b5 + lane);
    float v1 = -1e30f;
    if (lane < 8) v1 = pre[(size_t)node * 40 + 32 + lane] * 0.125f + __ldg(b5 + 32 + lane);
    float mx = fmaxf(v0, v1);
#pragma unroll
    for (int off = 16; off; off >>= 1) mx = fmaxf(mx, __shfl_xor_sync(0xffffffffu, mx, off));
    float sum = __expf(v0 - mx) + (lane < 8 ? __expf(v1 - mx) : 0.f);
#pragma unroll
    for (int off = 16; off; off >>= 1) sum += __shfl_xor_sync(0xffffffffu, sum, off);
    float lse = mx + __logf(sum);
    out[(size_t)node * 40 + lane] = v0 - lse;
    if (lane < 8) out[(size_t)node * 40 + 32 + lane] = v1 - lse;
}

// ---------------- host ----------------
static void* sym(const void* s) {
    void* p = nullptr;
    cudaGetSymbolAddress(&p, s);
    return p;
}

extern "C" void kernel_launch(void* const* d_in, const int* in_sizes, int n_in,
                              void* d_out, int out_size)
{
    const float* x   = (const float*)d_in[0];
    const int*   ei  = (const int*)d_in[1];
    const float* Ws[5]  = {(const float*)d_in[2],  (const float*)d_in[6],
                           (const float*)d_in[10], (const float*)d_in[14],
                           (const float*)d_in[18]};
    const float* asv[5] = {(const float*)d_in[3],  (const float*)d_in[7],
                           (const float*)d_in[11], (const float*)d_in[15],
                           (const float*)d_in[19]};
    const float* adv[5] = {(const float*)d_in[4],  (const float*)d_in[8],
                           (const float*)d_in[12], (const float*)d_in[16],
                           (const float*)d_in[20]};
    const float* bs[5]  = {(const float*)d_in[5],  (const float*)d_in[9],
                           (const float*)d_in[13], (const float*)d_in[17],
                           (const float*)d_in[21]};

    int n = in_sizes[0] / 128;
    int E = in_sizes[1] / 2;

    float* hfeat  = (float*)sym(g_hfeat);
    float* actA   = (float*)sym(g_actA);
    float* actB   = (float*)sym(g_actB);
    float* sbuf   = (float*)sym(g_s);
    float* alpha  = (float*)sym(g_alpha);
    int*   col    = (int*)  sym(g_col);
    int*   rowptr = (int*)  sym(g_rowptr);
    int*   cursor = (int*)  sym(g_cursor);
    int*   cnt    = (int*)  sym(g_cnt);
    float* ybuf   = (float*)sym(g_y);
    float* Wfold  = (float*)sym(g_Wfold);
    float* Wp     = (float*)sym(g_Wp);
    float* pre    = (float*)sym(g_pre);

    // ---- CSR build (dst-grouped) ----
    k_init_cnt<<<(n + 255) / 256, 256>>>(cnt, n);
    k_hist<<<(E + 255) / 256, 256>>>(ei + E, cnt, E);
    k_scan<<<1, 1024>>>(cnt, rowptr, cursor, n);
    k_scatter<<<(E + n + 255) / 256, 256>>>(ei, cursor, col, E, n);

    int warpBlocks = (n + 7) / 8;
    int rowGrid = (n + 127) / 128;

    // ---- layers 1..4 (concat, lrelu) ----
    const float* cur = x;
    int K = 128;
    float* acts[2] = {actA, actB};
    for (int L = 0; L < 4; L++) {
        k_fold<<<(K * 16 + 255) / 256, 256>>>(Ws[L], asv[L], adv[L], Wfold, K, 8);
        {   // s = cur @ Wfold  [n,16]  (exact-width tile)
            dim3 g(1, rowGrid);
            k_gemm<1><<<g, 256>>>(cur, Wfold, sbuf, n, 16, K);
        }
        {   // h = cur @ W  [n,64]
            dim3 g(1, rowGrid);
            k_gemm<4><<<g, 256>>>(cur, Ws[L], hfeat, n, 64, K);
        }
        k_agg_cat<<<warpBlocks, 256>>>(hfeat, sbuf, rowptr, col, bs[L],
                                       acts[L & 1], alpha, n);
        cur = acts[L & 1];
        K = 64;
    }

    // ---- layer 5: aggregate x4 per head, then block-diag GEMM ----
    k_fold<<<(64 * 16 + 255) / 256, 256>>>(Ws[4], asv[4], adv[4], Wfold, 64, 40);
    {
        dim3 g(1, rowGrid);
        k_gemm<1><<<g, 256>>>(cur, Wfold, sbuf, n, 16, 64);
    }
    k_agg_mean<<<warpBlocks, 256>>>(cur, sbuf, rowptr, col, ybuf, alpha, n);
    k_wprime<<<(512 * 40 + 255) / 256, 256>>>(Ws[4], Wp);
    {   // pre = y @ Wp  [n,40]  (BN=48 tile, minimal padding)
        dim3 g(1, rowGrid);
        k_gemm<3><<<g, 256>>>(ybuf, Wp, pre, n, 40, 512);
    }
    k_lsm<<<warpBlocks, 256>>>(pre, bs[4], (float*)d_out, n);
}

// round 5
// speedup vs baseline: 2.2698x; 1.3335x over previous
#include <cuda_runtime.h>
#include <cstddef>
#include <cstdint>

// Problem constants: N=50000, F=128, H=8, HID=8, CLS=40, E=1.6M
#define NMAX 50000
#define EMAX 1700000   // E + self loops head-room

// ---------------- static device scratch ----------------
__device__ float g_hs   [(size_t)NMAX * 80];   // fused GEMM out: [0..63]=h, [64..71]=s_src, [72..79]=s_dst
__device__ float g_actA [(size_t)NMAX * 64];
__device__ float g_actB [(size_t)NMAX * 64];
__device__ float g_sbuf [(size_t)NMAX * 16];   // layer-5 scores
__device__ float g_ex   [(size_t)EMAX * 8];    // layer-5 per-edge exp values
__device__ int   g_col  [EMAX];
__device__ int   g_rowptr[NMAX + 1];
__device__ int   g_cursor[NMAX];
__device__ int   g_cnt   [NMAX];
__device__ float g_y    [(size_t)NMAX * 512];  // layer-5 pre-GEMM aggregate [N,8,64]
__device__ float g_Bcat [128 * 80];            // [W | fold_src | fold_dst]
__device__ float g_Wfold[128 * 16];
__device__ float g_Wp   [512 * 40];
__device__ float g_pre  [(size_t)NMAX * 40];

// ---------------- CSR build ----------------
__global__ void k_init_cnt(int* cnt, int n) {
    int i = blockIdx.x * blockDim.x + threadIdx.x;
    if (i < n) cnt[i] = 1;                       // self loop
}

__global__ void k_hist(const int* __restrict__ dst, int* cnt, int E) {
    int i = blockIdx.x * blockDim.x + threadIdx.x;
    if (i < E) atomicAdd(&cnt[dst[i]], 1);
}

__global__ void k_scan(const int* __restrict__ cnt, int* rowptr, int* cursor, int n) {
    __shared__ int sm[1024];
    __shared__ int carry;
    int tid = threadIdx.x;
    if (tid == 0) carry = 0;
    __syncthreads();
    for (int base = 0; base < n; base += 1024) {
        int i = base + tid;
        int v = (i < n) ? cnt[i] : 0;
        sm[tid] = v;
        __syncthreads();
        for (int off = 1; off < 1024; off <<= 1) {
            int t = (tid >= off) ? sm[tid - off] : 0;
            __syncthreads();
            sm[tid] += t;
            __syncthreads();
        }
        int excl = carry + sm[tid] - v;
        if (i < n) { rowptr[i] = excl; cursor[i] = excl; }
        __syncthreads();
        if (tid == 0) carry += sm[1023];
        __syncthreads();
    }
    if (tid == 0) rowptr[n] = carry;
}

__global__ void k_scatter(const int* __restrict__ ei, int* cursor, int* col, int E, int n) {
    int i = blockIdx.x * blockDim.x + threadIdx.x;
    if (i < E) {
        int s = ei[i];
        int d = ei[E + i];
        int p = atomicAdd(&cursor[d], 1);
        col[p] = s;
    } else if (i < E + n) {
        int nd = i - E;
        int p = atomicAdd(&cursor[nd], 1);
        col[p] = nd;
    }
}

// ---------------- SGEMM: C[M,Nc] = A[M,K] @ B[K,Nc] ----------------
template<int TN>
__global__ __launch_bounds__(256) void k_gemm(
    const float* __restrict__ A, const float* __restrict__ B, float* __restrict__ C,
    int M, int Nc, int K)
{
    const int BN = 16 * TN;
    __shared__ float As[16][132];
    __shared__ float Bs[16][BN];
    int tid = threadIdx.x;
    int bm = blockIdx.y * 128;
    int bn = blockIdx.x * BN;
    int tx = tid & 15;
    int ty = tid >> 4;
    float acc[8][TN];
#pragma unroll
    for (int i = 0; i < 8; i++)
#pragma unroll
        for (int j = 0; j < TN; j++) acc[i][j] = 0.f;

    for (int k0 = 0; k0 < K; k0 += 16) {
#pragma unroll
        for (int it = 0; it < 2; it++) {
            int idx = tid + it * 256;
            int m  = idx >> 2;
            int kq = (idx & 3) * 4;
            int gm = bm + m;
            float4 v = make_float4(0.f, 0.f, 0.f, 0.f);
            if (gm < M) v = *(const float4*)(A + (size_t)gm * K + k0 + kq);
            As[kq + 0][m] = v.x;
            As[kq + 1][m] = v.y;
            As[kq + 2][m] = v.z;
            As[kq + 3][m] = v.w;
        }
        for (int idx = tid; idx < 16 * BN; idx += 256) {
            int kk = idx / BN;
            int cc = idx % BN;
            int gc = bn + cc;
            float v = 0.f;
            if (gc < Nc) v = B[(size_t)(k0 + kk) * Nc + gc];
            Bs[kk][cc] = v;
        }
        __syncthreads();
#pragma unroll
        for (int kk = 0; kk < 16; kk++) {
            float4 a0 = *(const float4*)(&As[kk][ty * 8]);
            float4 a1 = *(const float4*)(&As[kk][ty * 8 + 4]);
            float av[8] = {a0.x, a0.y, a0.z, a0.w, a1.x, a1.y, a1.z, a1.w};
            float bv[TN];
#pragma unroll
            for (int j = 0; j < TN; j++) bv[j] = Bs[kk][tx * TN + j];
#pragma unroll
            for (int i = 0; i < 8; i++)
#pragma unroll
                for (int j = 0; j < TN; j++) acc[i][j] += av[i] * bv[j];
        }
        __syncthreads();
    }
#pragma unroll
    for (int i = 0; i < 8; i++) {
        int gm = bm + ty * 8 + i;
        if (gm >= M) continue;
#pragma unroll
        for (int j = 0; j < TN; j++) {
            int gc = bn + tx * TN + j;
            if (gc < Nc) C[(size_t)gm * Nc + gc] = acc[i][j];
        }
    }
}

// ---------------- build Bcat = [W (64 cols) | fold_src (8) | fold_dst (8)] ------
__global__ void k_prep_bcat(const float* __restrict__ W, const float* __restrict__ a_src,
                            const float* __restrict__ a_dst, float* __restrict__ Bcat, int K)
{
    int idx = blockIdx.x * blockDim.x + threadIdx.x;
    if (idx >= K * 80) return;
    int k = idx / 80;
    int c = idx % 80;
    if (c < 64) {
        Bcat[idx] = W[(size_t)k * 64 + c];
    } else {
        int j = c - 64;
        int h = j & 7;
        const float* a = (j < 8) ? a_src : a_dst;
        float sum = 0.f;
#pragma unroll
        for (int q = 0; q < 8; q++)
            sum += W[(size_t)k * 64 + h * 8 + q] * a[h * 8 + q];
        Bcat[idx] = sum;
    }
}

// ---------------- layer-5 fold (C=40) ----------------
__global__ void k_fold(const float* __restrict__ W, const float* __restrict__ a_src,
                       const float* __restrict__ a_dst, float* __restrict__ Wf,
                       int K, int C)
{
    int idx = blockIdx.x * blockDim.x + threadIdx.x;
    if (idx >= K * 16) return;
    int k = idx >> 4;
    int j = idx & 15;
    int h = j & 7;
    const float* a = (j < 8) ? a_src : a_dst;
    float sum = 0.f;
    for (int c = 0; c < C; c++)
        sum += W[(size_t)k * 8 * C + h * C + c] * a[h * C + c];
    Wf[idx] = sum;
}

__global__ void k_wprime(const float* __restrict__ W5, float* __restrict__ Wp) {
    int idx = blockIdx.x * blockDim.x + threadIdx.x;
    if (idx >= 512 * 40) return;
    int kk = idx / 40;
    int c  = idx % 40;
    int h  = kk >> 6;
    int k  = kk & 63;
    Wp[idx] = W5[(size_t)k * 320 + h * 40 + c];
}

// ---------------- concat-layer aggregation: ONE PASS ----------------
// lane -> (head h, channel pair cb). Each lane accumulates weighted sum AND
// the softmax denominator simultaneously (no max subtraction; logits are small).
__global__ __launch_bounds__(256) void k_agg_cat(
    const float* __restrict__ hs, const int* __restrict__ rowptr,
    const int* __restrict__ colx, const float* __restrict__ bias,
    float* __restrict__ out, int n)
{
    int node = (blockIdx.x * blockDim.x + threadIdx.x) >> 5;
    if (node >= n) return;
    int lane = threadIdx.x & 31;
    int beg = rowptr[node], end = rowptr[node + 1];

    int h  = lane >> 2;
    int cb = (lane & 3) * 2;
    float sdv = __ldg(hs + (size_t)node * 80 + 72 + h);

    float a0 = 0.f, a1 = 0.f, d = 0.f;

    int e = beg;
    for (; e + 4 <= end; e += 4) {
        int si[4];
#pragma unroll
        for (int u = 0; u < 4; u++) si[u] = colx[e + u];
        float ss[4];
        float2 v[4];
#pragma unroll
        for (int u = 0; u < 4; u++) {
            const float* row = hs + (size_t)si[u] * 80;
            ss[u] = __ldg(row + 64 + h);
            v[u]  = *(const float2*)(row + h * 8 + cb);
        }
#pragma unroll
        for (int u = 0; u < 4; u++) {
            float al = ss[u] + sdv;
            al = al > 0.f ? al : 0.2f * al;
            float ex = __expf(al);
            d  += ex;
            a0 += ex * v[u].x;
            a1 += ex * v[u].y;
        }
    }
    for (; e < end; e++) {
        int si = colx[e];
        const float* row = hs + (size_t)si * 80;
        float ssv = __ldg(row + 64 + h);
        float2 v  = *(const float2*)(row + h * 8 + cb);
        float al = ssv + sdv;
        al = al > 0.f ? al : 0.2f * al;
        float ex = __expf(al);
        d  += ex;
        a0 += ex * v.x;
        a1 += ex * v.y;
    }

    float inv = 1.f / (d + 1e-16f);
    float r0 = a0 * inv + __ldg(bias + h * 8 + cb);
    float r1 = a1 * inv + __ldg(bias + h * 8 + cb + 1);
    r0 = r0 > 0.f ? r0 : 0.2f * r0;
    r1 = r1 > 0.f ? r1 : 0.2f * r1;
    size_t o = (size_t)node * 64 + h * 8 + cb;
    out[o]     = r0;
    out[o + 1] = r1;
}

// ---------------- layer-5 aggregation: y[N,8,64], two passes ----------------
// Pass 1 (edge-parallel across lanes): ex = exp(lrelu(logit)), denominators.
// Pass 2 (lane = channel pair): weighted aggregation reading broadcast ex rows.
__global__ __launch_bounds__(256) void k_agg_mean(
    const float* __restrict__ xin, const float* __restrict__ s,
    const int* __restrict__ rowptr, const int* __restrict__ colx,
    float* __restrict__ y, float* __restrict__ exbuf, int n)
{
    int node = (blockIdx.x * blockDim.x + threadIdx.x) >> 5;
    if (node >= n) return;
    int lane = threadIdx.x & 31;
    int beg = rowptr[node], end = rowptr[node + 1];

    float sdv[8];
    const float* sd = s + (size_t)node * 16 + 8;
#pragma unroll
    for (int h = 0; h < 8; h++) sdv[h] = __ldg(sd + h);

    float dsum[8];
#pragma unroll
    for (int h = 0; h < 8; h++) dsum[h] = 0.f;

    for (int e = beg + lane; e < end; e += 32) {
        int si = colx[e];
        const float4* sp = (const float4*)(s + (size_t)si * 16);
        float4 s0 = __ldg(sp);
        float4 s1 = __ldg(sp + 1);
        float ss[8] = {s0.x, s0.y, s0.z, s0.w, s1.x, s1.y, s1.z, s1.w};
        float ex[8];
#pragma unroll
        for (int h = 0; h < 8; h++) {
            float al = ss[h] + sdv[h];
            al = al > 0.f ? al : 0.2f * al;
            ex[h] = __expf(al);
            dsum[h] += ex[h];
        }
        float4* ep = (float4*)(exbuf + (size_t)e * 8);
        ep[0] = make_float4(ex[0], ex[1], ex[2], ex[3]);
        ep[1] = make_float4(ex[4], ex[5], ex[6], ex[7]);
    }
#pragma unroll
    for (int off = 16; off; off >>= 1)
#pragma unroll
        for (int h = 0; h < 8; h++)
            dsum[h] += __shfl_xor_sync(0xffffffffu, dsum[h], off);

    float inv[8];
#pragma unroll
    for (int h = 0; h < 8; h++) inv[h] = 1.f / (dsum[h] + 1e-16f);
    __syncwarp();

    int kb = lane * 2;
    float acc[8][2];
#pragma unroll
    for (int h = 0; h < 8; h++) { acc[h][0] = 0.f; acc[h][1] = 0.f; }

    int e = beg;
    for (; e + 2 <= end; e += 2) {
        int si0 = colx[e], si1 = colx[e + 1];
        const float4* ap0 = (const float4*)(exbuf + (size_t)e * 8);
        const float4* ap1 = (const float4*)(exbuf + (size_t)(e + 1) * 8);
        float4 q00 = __ldg(ap0), q01 = __ldg(ap0 + 1);
        float4 q10 = __ldg(ap1), q11 = __ldg(ap1 + 1);
        float2 v0 = *(const float2*)(xin + (size_t)si0 * 64 + kb);
        float2 v1 = *(const float2*)(xin + (size_t)si1 * 64 + kb);
        float a0[8] = {q00.x, q00.y, q00.z, q00.w, q01.x, q01.y, q01.z, q01.w};
        float a1[8] = {q10.x, q10.y, q10.z, q10.w, q11.x, q11.y, q11.z, q11.w};
#pragma unroll
        for (int h = 0; h < 8; h++) {
            acc[h][0] += a0[h] * v0.x + a1[h] * v1.x;
            acc[h][1] += a0[h] * v0.y + a1[h] * v1.y;
        }
    }
    for (; e < end; e++) {
        int si = colx[e];
        const float4* ap = (const float4*)(exbuf + (size_t)e * 8);
        float4 q0 = __ldg(ap), q1 = __ldg(ap + 1);
        float2 v = *(const float2*)(xin + (size_t)si * 64 + kb);
        float av[8] = {q0.x, q0.y, q0.z, q0.w, q1.x, q1.y, q1.z, q1.w};
#pragma unroll
        for (int h = 0; h < 8; h++) {
            acc[h][0] += av[h] * v.x;
            acc[h][1] += av[h] * v.y;
        }
    }
#pragma unroll
    for (int h = 0; h < 8; h++) {
        size_t o = (size_t)node * 512 + h * 64 + kb;
        y[o]     = acc[h][0] * inv[h];
        y[o + 1] = acc[h][1] * inv[h];
    }
}

// ---------------- final: mean(/8) + b5 + log_softmax ----------------
__global__ __launch_bounds__(256) void k_lsm(
    const float* __restrict__ pre, const float* __restrict__ b5,
    float* __restrict__ out, int n)
{
    int node = (blockIdx.x * blockDim.x + threadIdx.x) >> 5;
    if (node >= n) return;
    int lane = threadIdx.x & 31;
    float v0 = pre[(size_t)node * 40 + lane] * 0.125f + __ldg(b5 + lane);
    float v1 = -1e30f;
    if (lane < 8) v1 = pre[(size_t)node * 40 + 32 + lane] * 0.125f + __ldg(b5 + 32 + lane);
    float mx = fmaxf(v0, v1);
#pragma unroll
    for (int off = 16; off; off >>= 1) mx = fmaxf(mx, __shfl_xor_sync(0xffffffffu, mx, off));
    float sum = __expf(v0 - mx) + (lane < 8 ? __expf(v1 - mx) : 0.f);
#pragma unroll
    for (int off = 16; off; off >>= 1) sum += __shfl_xor_sync(0xffffffffu, sum, off);
    float lse = mx + __logf(sum);
    out[(size_t)node * 40 + lane] = v0 - lse;
    if (lane < 8) out[(size_t)node * 40 + 32 + lane] = v1 - lse;
}

// ---------------- host ----------------
static void* sym(const void* s) {
    void* p = nullptr;
    cudaGetSymbolAddress(&p, s);
    return p;
}

extern "C" void kernel_launch(void* const* d_in, const int* in_sizes, int n_in,
                              void* d_out, int out_size)
{
    const float* x   = (const float*)d_in[0];
    const int*   ei  = (const int*)d_in[1];
    const float* Ws[5]  = {(const float*)d_in[2],  (const float*)d_in[6],
                           (const float*)d_in[10], (const float*)d_in[14],
                           (const float*)d_in[18]};
    const float* asv[5] = {(const float*)d_in[3],  (const float*)d_in[7],
                           (const float*)d_in[11], (const float*)d_in[15],
                           (const float*)d_in[19]};
    const float* adv[5] = {(const float*)d_in[4],  (const float*)d_in[8],
                           (const float*)d_in[12], (const float*)d_in[16],
                           (const float*)d_in[20]};
    const float* bs[5]  = {(const float*)d_in[5],  (const float*)d_in[9],
                           (const float*)d_in[13], (const float*)d_in[17],
                           (const float*)d_in[21]};

    int n = in_sizes[0] / 128;
    int E = in_sizes[1] / 2;

    float* hs     = (float*)sym(g_hs);
    float* actA   = (float*)sym(g_actA);
    float* actB   = (float*)sym(g_actB);
    float* sbuf   = (float*)sym(g_sbuf);
    float* exbuf  = (float*)sym(g_ex);
    int*   col    = (int*)  sym(g_col);
    int*   rowptr = (int*)  sym(g_rowptr);
    int*   cursor = (int*)  sym(g_cursor);
    int*   cnt    = (int*)  sym(g_cnt);
    float* ybuf   = (float*)sym(g_y);
    float* Bcat   = (float*)sym(g_Bcat);
    float* Wfold  = (float*)sym(g_Wfold);
    float* Wp     = (float*)sym(g_Wp);
    float* pre    = (float*)sym(g_pre);

    // ---- CSR build (dst-grouped) ----
    k_init_cnt<<<(n + 255) / 256, 256>>>(cnt, n);
    k_hist<<<(E + 255) / 256, 256>>>(ei + E, cnt, E);
    k_scan<<<1, 1024>>>(cnt, rowptr, cursor, n);
    k_scatter<<<(E + n + 255) / 256, 256>>>(ei, cursor, col, E, n);

    int warpBlocks = (n + 7) / 8;
    int rowGrid = (n + 127) / 128;

    // ---- layers 1..4: fused [h|s] GEMM + one-pass aggregate ----
    const float* cur = x;
    int K = 128;
    float* acts[2] = {actA, actB};
    for (int L = 0; L < 4; L++) {
        k_prep_bcat<<<(K * 80 + 255) / 256, 256>>>(Ws[L], asv[L], adv[L], Bcat, K);
        {
            dim3 g(1, rowGrid);
            k_gemm<5><<<g, 256>>>(cur, Bcat, hs, n, 80, K);
        }
        k_agg_cat<<<warpBlocks, 256>>>(hs, rowptr, col, bs[L], acts[L & 1], n);
        cur = acts[L & 1];
        K = 64;
    }

    // ---- layer 5: aggregate x4 per head, then block-diag GEMM ----
    k_fold<<<(64 * 16 + 255) / 256, 256>>>(Ws[4], asv[4], adv[4], Wfold, 64, 40);
    {
        dim3 g(1, rowGrid);
        k_gemm<1><<<g, 256>>>(cur, Wfold, sbuf, n, 16, 64);
    }
    k_agg_mean<<<warpBlocks, 256>>>(cur, sbuf, rowptr, col, ybuf, exbuf, n);
    k_wprime<<<(512 * 40 + 255) / 256, 256>>>(Ws[4], Wp);
    {
        dim3 g(1, rowGrid);
        k_gemm<3><<<g, 256>>>(ybuf, Wp, pre, n, 40, 512);
    }
    k_lsm<<<warpBlocks, 256>>>(pre, bs[4], (float*)d_out, n);
}

// round 6
// speedup vs baseline: 2.7931x; 1.2306x over previous
#include <cuda_runtime.h>
#include <cstddef>
#include <cstdint>

// Problem constants: N=50000, F=128, H=8, HID=8, CLS=40, E=1.6M
#define NMAX 50000
#define EMAX 1700000   // E + self loops head-room

// ---------------- static device scratch ----------------
__device__ float g_hs   [(size_t)NMAX * 80];   // [0..63]=h, [64..71]=s_src, [72..79]=s_dst
__device__ float g_actA [(size_t)NMAX * 64];
__device__ float g_actB [(size_t)NMAX * 64];
__device__ float g_sbuf [(size_t)NMAX * 16];
__device__ float g_ex   [(size_t)EMAX * 8];
__device__ int   g_col  [EMAX];
__device__ int   g_rowptr[NMAX + 1];
__device__ int   g_cursor[NMAX];
__device__ int   g_cnt   [NMAX];
__device__ int   g_bsum [64];
__device__ float g_y    [(size_t)NMAX * 512];
__device__ float g_Bcat [128 * 80];
__device__ float g_Wfold[128 * 16];
__device__ float g_Wp   [512 * 40];
__device__ float g_pre  [(size_t)NMAX * 40];

// ---------------- CSR build ----------------
__global__ void k_init_cnt(int* cnt, int n) {
    int i = blockIdx.x * blockDim.x + threadIdx.x;
    if (i < n) cnt[i] = 1;                       // self loop
}

__global__ void k_hist(const int* __restrict__ dst, int* cnt, int E) {
    int i = blockIdx.x * blockDim.x + threadIdx.x;
    if (i < E) atomicAdd(&cnt[dst[i]], 1);
}

// multi-block scan: stage 1 — per-block exclusive scan + block totals
__global__ void k_scan1(const int* __restrict__ cnt, int* rowptr, int* bsum, int n) {
    __shared__ int sm[1024];
    int tid = threadIdx.x;
    int i = blockIdx.x * 1024 + tid;
    int v = (i < n) ? cnt[i] : 0;
    sm[tid] = v;
    __syncthreads();
    for (int off = 1; off < 1024; off <<= 1) {
        int t = (tid >= off) ? sm[tid - off] : 0;
        __syncthreads();
        sm[tid] += t;
        __syncthreads();
    }
    if (i < n) rowptr[i] = sm[tid] - v;          // local exclusive
    if (tid == 1023) bsum[blockIdx.x] = sm[1023];
}

// stage 2 — scan the (<=64) block totals
__global__ void k_scan2(int* bsum, int nb) {
    __shared__ int sm[64];
    int tid = threadIdx.x;
    sm[tid] = (tid < nb) ? bsum[tid] : 0;
    __syncthreads();
    if (tid == 0) {
        int run = 0;
        for (int j = 0; j < nb; j++) { int t = sm[j]; sm[j] = run; run += t; }
    }
    __syncthreads();
    if (tid < nb) bsum[tid] = sm[tid];
}

// stage 3 — add block offsets, write cursor + rowptr[n]
__global__ void k_scan3(int* rowptr, int* cursor, const int* __restrict__ bsum,
                        const int* __restrict__ cnt, int n) {
    int i = blockIdx.x * blockDim.x + threadIdx.x;
    if (i < n) {
        int v = rowptr[i] + bsum[i >> 10];
        rowptr[i] = v;
        cursor[i] = v;
        if (i == n - 1) rowptr[n] = v + cnt[i];
    }
}

__global__ void k_scatter(const int* __restrict__ ei, int* cursor, int* col, int E, int n) {
    int i = blockIdx.x * blockDim.x + threadIdx.x;
    if (i < E) {
        int s = ei[i];
        int d = ei[E + i];
        int p = atomicAdd(&cursor[d], 1);
        col[p] = s;
    } else if (i < E + n) {
        int nd = i - E;
        int p = atomicAdd(&cursor[nd], 1);
        col[p] = nd;
    }
}

// ---------------- SGEMM: C[M,Nc] = A[M,K] @ B[K,Nc] ----------------
template<int TN>
__global__ __launch_bounds__(256) void k_gemm(
    const float* __restrict__ A, const float* __restrict__ B, float* __restrict__ C,
    int M, int Nc, int K)
{
    const int BN = 16 * TN;
    __shared__ float As[16][132];
    __shared__ float Bs[16][BN];
    int tid = threadIdx.x;
    int bm = blockIdx.y * 128;
    int bn = blockIdx.x * BN;
    int tx = tid & 15;
    int ty = tid >> 4;
    float acc[8][TN];
#pragma unroll
    for (int i = 0; i < 8; i++)
#pragma unroll
        for (int j = 0; j < TN; j++) acc[i][j] = 0.f;

    for (int k0 = 0; k0 < K; k0 += 16) {
#pragma unroll
        for (int it = 0; it < 2; it++) {
            int idx = tid + it * 256;
            int m  = idx >> 2;
            int kq = (idx & 3) * 4;
            int gm = bm + m;
            float4 v = make_float4(0.f, 0.f, 0.f, 0.f);
            if (gm < M) v = *(const float4*)(A + (size_t)gm * K + k0 + kq);
            As[kq + 0][m] = v.x;
            As[kq + 1][m] = v.y;
            As[kq + 2][m] = v.z;
            As[kq + 3][m] = v.w;
        }
        for (int idx = tid; idx < 16 * BN; idx += 256) {
            int kk = idx / BN;
            int cc = idx % BN;
            int gc = bn + cc;
            float v = 0.f;
            if (gc < Nc) v = B[(size_t)(k0 + kk) * Nc + gc];
            Bs[kk][cc] = v;
        }
        __syncthreads();
#pragma unroll
        for (int kk = 0; kk < 16; kk++) {
            float4 a0 = *(const float4*)(&As[kk][ty * 8]);
            float4 a1 = *(const float4*)(&As[kk][ty * 8 + 4]);
            float av[8] = {a0.x, a0.y, a0.z, a0.w, a1.x, a1.y, a1.z, a1.w};
            float bv[TN];
#pragma unroll
            for (int j = 0; j < TN; j++) bv[j] = Bs[kk][tx * TN + j];
#pragma unroll
            for (int i = 0; i < 8; i++)
#pragma unroll
                for (int j = 0; j < TN; j++) acc[i][j] += av[i] * bv[j];
        }
        __syncthreads();
    }
#pragma unroll
    for (int i = 0; i < 8; i++) {
        int gm = bm + ty * 8 + i;
        if (gm >= M) continue;
#pragma unroll
        for (int j = 0; j < TN; j++) {
            int gc = bn + tx * TN + j;
            if (gc < Nc) C[(size_t)gm * Nc + gc] = acc[i][j];
        }
    }
}

// ---------------- build Bcat = [W | fold_src | fold_dst] ----------------
__global__ void k_prep_bcat(const float* __restrict__ W, const float* __restrict__ a_src,
                            const float* __restrict__ a_dst, float* __restrict__ Bcat, int K)
{
    int idx = blockIdx.x * blockDim.x + threadIdx.x;
    if (idx >= K * 80) return;
    int k = idx / 80;
    int c = idx % 80;
    if (c < 64) {
        Bcat[idx] = W[(size_t)k * 64 + c];
    } else {
        int j = c - 64;
        int h = j & 7;
        const float* a = (j < 8) ? a_src : a_dst;
        float sum = 0.f;
#pragma unroll
        for (int q = 0; q < 8; q++)
            sum += W[(size_t)k * 64 + h * 8 + q] * a[h * 8 + q];
        Bcat[idx] = sum;
    }
}

__global__ void k_fold(const float* __restrict__ W, const float* __restrict__ a_src,
                       const float* __restrict__ a_dst, float* __restrict__ Wf,
                       int K, int C)
{
    int idx = blockIdx.x * blockDim.x + threadIdx.x;
    if (idx >= K * 16) return;
    int k = idx >> 4;
    int j = idx & 15;
    int h = j & 7;
    const float* a = (j < 8) ? a_src : a_dst;
    float sum = 0.f;
    for (int c = 0; c < C; c++)
        sum += W[(size_t)k * 8 * C + h * C + c] * a[h * C + c];
    Wf[idx] = sum;
}

__global__ void k_wprime(const float* __restrict__ W5, float* __restrict__ Wp) {
    int idx = blockIdx.x * blockDim.x + threadIdx.x;
    if (idx >= 512 * 40) return;
    int kk = idx / 40;
    int c  = idx % 40;
    int h  = kk >> 6;
    int k  = kk & 63;
    Wp[idx] = W5[(size_t)k * 320 + h * 40 + c];
}

// ---------------- concat-layer aggregation: one pass, 2 edges/warp-iter -------
// lane = (sub, h, q): sub=edge slot (16 lanes each), h=head, q=float4 quad.
__global__ __launch_bounds__(256) void k_agg_cat(
    const float* __restrict__ hs, const int* __restrict__ rowptr,
    const int* __restrict__ colx, const float* __restrict__ bias,
    float* __restrict__ out, int n)
{
    int node = (blockIdx.x * blockDim.x + threadIdx.x) >> 5;
    if (node >= n) return;
    int lane = threadIdx.x & 31;
    int beg = rowptr[node], end = rowptr[node + 1];

    int sub = lane >> 4;
    int r   = lane & 15;
    int h   = r >> 1;
    int q   = r & 1;
    float sdv = __ldg(hs + (size_t)node * 80 + 72 + h);

    float4 acc = make_float4(0.f, 0.f, 0.f, 0.f);
    float d = 0.f;

    int e0 = beg;
    // main loop: 4 edges per iteration, all in-range
    for (; e0 + 4 <= end; e0 += 4) {
        int siA = __ldg(colx + e0 + sub);
        int siB = __ldg(colx + e0 + 2 + sub);
        const float* rA = hs + (size_t)siA * 80;
        const float* rB = hs + (size_t)siB * 80;
        float sA = __ldg(rA + 64 + h);
        float sB = __ldg(rB + 64 + h);
        float4 vA = __ldg((const float4*)(rA + h * 8 + q * 4));
        float4 vB = __ldg((const float4*)(rB + h * 8 + q * 4));
        float aA = sA + sdv; aA = aA > 0.f ? aA : 0.2f * aA;
        float aB = sB + sdv; aB = aB > 0.f ? aB : 0.2f * aB;
        float eA = __expf(aA);
        float eB = __expf(aB);
        if (q == 0) d += eA + eB;
        acc.x += eA * vA.x + eB * vB.x;
        acc.y += eA * vA.y + eB * vB.y;
        acc.z += eA * vA.z + eB * vB.z;
        acc.w += eA * vA.w + eB * vB.w;
    }
    // tail: guarded pairs
    for (; e0 < end; e0 += 2) {
        int ee = e0 + sub;
        bool ok = ee < end;
        int si = ok ? __ldg(colx + ee) : node;
        const float* row = hs + (size_t)si * 80;
        float ssv = __ldg(row + 64 + h);
        float4 v  = __ldg((const float4*)(row + h * 8 + q * 4));
        float al = ssv + sdv; al = al > 0.f ? al : 0.2f * al;
        float ex = ok ? __expf(al) : 0.f;
        if (q == 0) d += ex;
        acc.x += ex * v.x;
        acc.y += ex * v.y;
        acc.z += ex * v.z;
        acc.w += ex * v.w;
    }

    // reduce across sub halves
    acc.x += __shfl_xor_sync(0xffffffffu, acc.x, 16);
    acc.y += __shfl_xor_sync(0xffffffffu, acc.y, 16);
    acc.z += __shfl_xor_sync(0xffffffffu, acc.z, 16);
    acc.w += __shfl_xor_sync(0xffffffffu, acc.w, 16);
    d     += __shfl_xor_sync(0xffffffffu, d, 16);
    // denominator lives on q==0 lanes; share with q==1 partner
    d     += __shfl_xor_sync(0xffffffffu, d, 1);

    if (sub == 0) {
        float inv = 1.f / (d + 1e-16f);
        int ch = h * 8 + q * 4;
        float4 b = __ldg((const float4*)(bias + ch));
        float4 rv;
        rv.x = acc.x * inv + b.x;
        rv.y = acc.y * inv + b.y;
        rv.z = acc.z * inv + b.z;
        rv.w = acc.w * inv + b.w;
        rv.x = rv.x > 0.f ? rv.x : 0.2f * rv.x;
        rv.y = rv.y > 0.f ? rv.y : 0.2f * rv.y;
        rv.z = rv.z > 0.f ? rv.z : 0.2f * rv.z;
        rv.w = rv.w > 0.f ? rv.w : 0.2f * rv.w;
        *(float4*)(out + (size_t)node * 64 + ch) = rv;
    }
}

// ---------------- layer-5 aggregation: y[N,8,64] ----------------
// Pass 1: lane-parallel ex + denominators. Pass 2: 2 edges/warp-iter, float4.
__global__ __launch_bounds__(256) void k_agg_mean(
    const float* __restrict__ xin, const float* __restrict__ s,
    const int* __restrict__ rowptr, const int* __restrict__ colx,
    float* __restrict__ y, float* __restrict__ exbuf, int n)
{
    int node = (blockIdx.x * blockDim.x + threadIdx.x) >> 5;
    if (node >= n) return;
    int lane = threadIdx.x & 31;
    int beg = rowptr[node], end = rowptr[node + 1];

    float sdv[8];
    const float* sd = s + (size_t)node * 16 + 8;
#pragma unroll
    for (int h = 0; h < 8; h++) sdv[h] = __ldg(sd + h);

    float dsum[8];
#pragma unroll
    for (int h = 0; h < 8; h++) dsum[h] = 0.f;

    for (int e = beg + lane; e < end; e += 32) {
        int si = colx[e];
        const float4* sp = (const float4*)(s + (size_t)si * 16);
        float4 s0 = __ldg(sp);
        float4 s1 = __ldg(sp + 1);
        float ss[8] = {s0.x, s0.y, s0.z, s0.w, s1.x, s1.y, s1.z, s1.w};
        float ex[8];
#pragma unroll
        for (int h = 0; h < 8; h++) {
            float al = ss[h] + sdv[h];
            al = al > 0.f ? al : 0.2f * al;
            ex[h] = __expf(al);
            dsum[h] += ex[h];
        }
        float4* ep = (float4*)(exbuf + (size_t)e * 8);
        ep[0] = make_float4(ex[0], ex[1], ex[2], ex[3]);
        ep[1] = make_float4(ex[4], ex[5], ex[6], ex[7]);
    }
#pragma unroll
    for (int off = 16; off; off >>= 1)
#pragma unroll
        for (int h = 0; h < 8; h++)
            dsum[h] += __shfl_xor_sync(0xffffffffu, dsum[h], off);

    float inv[8];
#pragma unroll
    for (int h = 0; h < 8; h++) inv[h] = 1.f / (dsum[h] + 1e-16f);
    __syncwarp();

    // pass 2: sub = edge slot, r = channel quad (16 lanes x float4 = 64 ch)
    int sub = lane >> 4;
    int kb  = (lane & 15) * 4;

    float4 acc8[8];
#pragma unroll
    for (int h = 0; h < 8; h++) acc8[h] = make_float4(0.f, 0.f, 0.f, 0.f);

    int e0 = beg;
    for (; e0 + 2 <= end; e0 += 2) {
        int ee = e0 + sub;
        int si = __ldg(colx + ee);
        const float4* ap = (const float4*)(exbuf + (size_t)ee * 8);
        float4 q0 = __ldg(ap);
        float4 q1 = __ldg(ap + 1);
        float4 v  = __ldg((const float4*)(xin + (size_t)si * 64 + kb));
        float av[8] = {q0.x, q0.y, q0.z, q0.w, q1.x, q1.y, q1.z, q1.w};
#pragma unroll
        for (int h = 0; h < 8; h++) {
            acc8[h].x += av[h] * v.x;
            acc8[h].y += av[h] * v.y;
            acc8[h].z += av[h] * v.z;
            acc8[h].w += av[h] * v.w;
        }
    }
    if (e0 < end && sub == 0) {        // odd remainder: sub 0 only
        int si = __ldg(colx + e0);
        const float4* ap = (const float4*)(exbuf + (size_t)e0 * 8);
        float4 q0 = __ldg(ap);
        float4 q1 = __ldg(ap + 1);
        float4 v  = __ldg((const float4*)(xin + (size_t)si * 64 + kb));
        float av[8] = {q0.x, q0.y, q0.z, q0.w, q1.x, q1.y, q1.z, q1.w};
#pragma unroll
        for (int h = 0; h < 8; h++) {
            acc8[h].x += av[h] * v.x;
            acc8[h].y += av[h] * v.y;
            acc8[h].z += av[h] * v.z;
            acc8[h].w += av[h] * v.w;
        }
    }

#pragma unroll
    for (int h = 0; h < 8; h++) {
        acc8[h].x += __shfl_xor_sync(0xffffffffu, acc8[h].x, 16);
        acc8[h].y += __shfl_xor_sync(0xffffffffu, acc8[h].y, 16);
        acc8[h].z += __shfl_xor_sync(0xffffffffu, acc8[h].z, 16);
        acc8[h].w += __shfl_xor_sync(0xffffffffu, acc8[h].w, 16);
    }

    if (sub == 0) {
#pragma unroll
        for (int h = 0; h < 8; h++) {
            float4 w;
            w.x = acc8[h].x * inv[h];
            w.y = acc8[h].y * inv[h];
            w.z = acc8[h].z * inv[h];
            w.w = acc8[h].w * inv[h];
            *(float4*)(y + (size_t)node * 512 + (size_t)h * 64 + kb) = w;
        }
    }
}

// ---------------- final: mean(/8) + b5 + log_softmax ----------------
__global__ __launch_bounds__(256) void k_lsm(
    const float* __restrict__ pre, const float* __restrict__ b5,
    float* __restrict__ out, int n)
{
    int node = (blockIdx.x * blockDim.x + threadIdx.x) >> 5;
    if (node >= n) return;
    int lane = threadIdx.x & 31;
    float v0 = pre[(size_t)node * 40 + lane] * 0.125f + __ldg(b5 + lane);
    float v1 = -1e30f;
    if (lane < 8) v1 = pre[(size_t)node * 40 + 32 + lane] * 0.125f + __ldg(b5 + 32 + lane);
    float mx = fmaxf(v0, v1);
#pragma unroll
    for (int off = 16; off; off >>= 1) mx = fmaxf(mx, __shfl_xor_sync(0xffffffffu, mx, off));
    float sum = __expf(v0 - mx) + (lane < 8 ? __expf(v1 - mx) : 0.f);
#pragma unroll
    for (int off = 16; off; off >>= 1) sum += __shfl_xor_sync(0xffffffffu, sum, off);
    float lse = mx + __logf(sum);
    out[(size_t)node * 40 + lane] = v0 - lse;
    if (lane < 8) out[(size_t)node * 40 + 32 + lane] = v1 - lse;
}

// ---------------- host ----------------
static void* sym(const void* s) {
    void* p = nullptr;
    cudaGetSymbolAddress(&p, s);
    return p;
}

extern "C" void kernel_launch(void* const* d_in, const int* in_sizes, int n_in,
                              void* d_out, int out_size)
{
    const float* x   = (const float*)d_in[0];
    const int*   ei  = (const int*)d_in[1];
    const float* Ws[5]  = {(const float*)d_in[2],  (const float*)d_in[6],
                           (const float*)d_in[10], (const float*)d_in[14],
                           (const float*)d_in[18]};
    const float* asv[5] = {(const float*)d_in[3],  (const float*)d_in[7],
                           (const float*)d_in[11], (const float*)d_in[15],
                           (const float*)d_in[19]};
    const float* adv[5] = {(const float*)d_in[4],  (const float*)d_in[8],
                           (const float*)d_in[12], (const float*)d_in[16],
                           (const float*)d_in[20]};
    const float* bs[5]  = {(const float*)d_in[5],  (const float*)d_in[9],
                           (const float*)d_in[13], (const float*)d_in[17],
                           (const float*)d_in[21]};

    int n = in_sizes[0] / 128;
    int E = in_sizes[1] / 2;

    float* hs     = (float*)sym(g_hs);
    float* actA   = (float*)sym(g_actA);
    float* actB   = (float*)sym(g_actB);
    float* sbuf   = (float*)sym(g_sbuf);
    float* exbuf  = (float*)sym(g_ex);
    int*   col    = (int*)  sym(g_col);
    int*   rowptr = (int*)  sym(g_rowptr);
    int*   cursor = (int*)  sym(g_cursor);
    int*   cnt    = (int*)  sym(g_cnt);
    int*   bsum   = (int*)  sym(g_bsum);
    float* ybuf   = (float*)sym(g_y);
    float* Bcat   = (float*)sym(g_Bcat);
    float* Wfold  = (float*)sym(g_Wfold);
    float* Wp     = (float*)sym(g_Wp);
    float* pre    = (float*)sym(g_pre);

    // ---- CSR build (dst-grouped) ----
    int nb = (n + 1023) / 1024;
    k_init_cnt<<<(n + 255) / 256, 256>>>(cnt, n);
    k_hist<<<(E + 255) / 256, 256>>>(ei + E, cnt, E);
    k_scan1<<<nb, 1024>>>(cnt, rowptr, bsum, n);
    k_scan2<<<1, 64>>>(bsum, nb);
    k_scan3<<<(n + 255) / 256, 256>>>(rowptr, cursor, bsum, cnt, n);
    k_scatter<<<(E + n + 255) / 256, 256>>>(ei, cursor, col, E, n);

    int warpBlocks = (n + 7) / 8;
    int rowGrid = (n + 127) / 128;

    // ---- layers 1..4: fused [h|s] GEMM + one-pass aggregate ----
    const float* cur = x;
    int K = 128;
    float* acts[2] = {actA, actB};
    for (int L = 0; L < 4; L++) {
        k_prep_bcat<<<(K * 80 + 255) / 256, 256>>>(Ws[L], asv[L], adv[L], Bcat, K);
        {
            dim3 g(1, rowGrid);
            k_gemm<5><<<g, 256>>>(cur, Bcat, hs, n, 80, K);
        }
        k_agg_cat<<<warpBlocks, 256>>>(hs, rowptr, col, bs[L], acts[L & 1], n);
        cur = acts[L & 1];
        K = 64;
    }

    // ---- layer 5: aggregate x4 per head, then block-diag GEMM ----
    k_fold<<<(64 * 16 + 255) / 256, 256>>>(Ws[4], asv[4], adv[4], Wfold, 64, 40);
    {
        dim3 g(1, rowGrid);
        k_gemm<1><<<g, 256>>>(cur, Wfold, sbuf, n, 16, 64);
    }
    k_agg_mean<<<warpBlocks, 256>>>(cur, sbuf, rowptr, col, ybuf, exbuf, n);
    k_wprime<<<(512 * 40 + 255) / 256, 256>>>(Ws[4], Wp);
    {
        dim3 g(1, rowGrid);
        k_gemm<3><<<g, 256>>>(ybuf, Wp, pre, n, 40, 512);
    }
    k_lsm<<<warpBlocks, 256>>>(pre, bs[4], (float*)d_out, n);
}

// round 7
// speedup vs baseline: 2.9488x; 1.0557x over previous
#include <cuda_runtime.h>
#include <cuda_bf16.h>
#include <cstddef>
#include <cstdint>

// Problem constants: N=50000, F=128, H=8, HID=8, CLS=40, E=1.6M
#define NMAX 50000
#define EMAX 1700000

// ---------------- static device scratch ----------------
__device__ float g_hs   [(size_t)NMAX * 80];   // [0..63]=h, [64..71]=s_src, [72..79]=s_dst
__device__ float g_actA [(size_t)NMAX * 64];
__device__ float g_actB [(size_t)NMAX * 64];
__device__ float g_sbuf [(size_t)NMAX * 16];
__device__ float g_ex   [(size_t)EMAX * 8];
__device__ int   g_col  [EMAX];
__device__ int   g_rowptr[NMAX + 1];
__device__ int   g_cursor[NMAX];
__device__ int   g_cnt   [NMAX];
__device__ int   g_bsum [64];
__device__ __nv_bfloat16 g_yh[(size_t)NMAX * 512];  // layer-5 aggregate, bf16 hi plane
__device__ __nv_bfloat16 g_yl[(size_t)NMAX * 512];  // bf16 lo plane (residual)
__device__ __nv_bfloat16 g_Wth[40 * 512];           // W5 transposed block-diag, hi
__device__ __nv_bfloat16 g_Wtl[40 * 512];           // lo
__device__ float g_Bcat [128 * 80];
__device__ float g_Wfold[128 * 16];

// ---------------- CSR build ----------------
__global__ void k_init_cnt(int* cnt, int n) {
    int i = blockIdx.x * blockDim.x + threadIdx.x;
    if (i < n) cnt[i] = 1;
}

__global__ void k_hist(const int* __restrict__ dst, int* cnt, int E) {
    int i = blockIdx.x * blockDim.x + threadIdx.x;
    if (i < E) atomicAdd(&cnt[dst[i]], 1);
}

__global__ void k_scan1(const int* __restrict__ cnt, int* rowptr, int* bsum, int n) {
    __shared__ int sm[1024];
    int tid = threadIdx.x;
    int i = blockIdx.x * 1024 + tid;
    int v = (i < n) ? cnt[i] : 0;
    sm[tid] = v;
    __syncthreads();
    for (int off = 1; off < 1024; off <<= 1) {
        int t = (tid >= off) ? sm[tid - off] : 0;
        __syncthreads();
        sm[tid] += t;
        __syncthreads();
    }
    if (i < n) rowptr[i] = sm[tid] - v;
    if (tid == 1023) bsum[blockIdx.x] = sm[1023];
}

__global__ void k_scan2(int* bsum, int nb) {
    __shared__ int sm[64];
    int tid = threadIdx.x;
    sm[tid] = (tid < nb) ? bsum[tid] : 0;
    __syncthreads();
    if (tid == 0) {
        int run = 0;
        for (int j = 0; j < nb; j++) { int t = sm[j]; sm[j] = run; run += t; }
    }
    __syncthreads();
    if (tid < nb) bsum[tid] = sm[tid];
}

__global__ void k_scan3(int* rowptr, int* cursor, const int* __restrict__ bsum,
                        const int* __restrict__ cnt, int n) {
    int i = blockIdx.x * blockDim.x + threadIdx.x;
    if (i < n) {
        int v = rowptr[i] + bsum[i >> 10];
        rowptr[i] = v;
        cursor[i] = v;
        if (i == n - 1) rowptr[n] = v + cnt[i];
    }
}

__global__ void k_scatter(const int* __restrict__ ei, int* cursor, int* col, int E, int n) {
    int i = blockIdx.x * blockDim.x + threadIdx.x;
    if (i < E) {
        int s = ei[i];
        int d = ei[E + i];
        int p = atomicAdd(&cursor[d], 1);
        col[p] = s;
    } else if (i < E + n) {
        int nd = i - E;
        int p = atomicAdd(&cursor[nd], 1);
        col[p] = nd;
    }
}

// ---------------- SGEMM: C[M,Nc] = A[M,K] @ B[K,Nc] ----------------
template<int TN>
__global__ __launch_bounds__(256) void k_gemm(
    const float* __restrict__ A, const float* __restrict__ B, float* __restrict__ C,
    int M, int Nc, int K)
{
    const int BN = 16 * TN;
    __shared__ float As[16][132];
    __shared__ float Bs[16][BN];
    int tid = threadIdx.x;
    int bm = blockIdx.y * 128;
    int bn = blockIdx.x * BN;
    int tx = tid & 15;
    int ty = tid >> 4;
    float acc[8][TN];
#pragma unroll
    for (int i = 0; i < 8; i++)
#pragma unroll
        for (int j = 0; j < TN; j++) acc[i][j] = 0.f;

    for (int k0 = 0; k0 < K; k0 += 16) {
#pragma unroll
        for (int it = 0; it < 2; it++) {
            int idx = tid + it * 256;
            int m  = idx >> 2;
            int kq = (idx & 3) * 4;
            int gm = bm + m;
            float4 v = make_float4(0.f, 0.f, 0.f, 0.f);
            if (gm < M) v = *(const float4*)(A + (size_t)gm * K + k0 + kq);
            As[kq + 0][m] = v.x;
            As[kq + 1][m] = v.y;
            As[kq + 2][m] = v.z;
            As[kq + 3][m] = v.w;
        }
        for (int idx = tid; idx < 16 * BN; idx += 256) {
            int kk = idx / BN;
            int cc = idx % BN;
            int gc = bn + cc;
            float v = 0.f;
            if (gc < Nc) v = B[(size_t)(k0 + kk) * Nc + gc];
            Bs[kk][cc] = v;
        }
        __syncthreads();
#pragma unroll
        for (int kk = 0; kk < 16; kk++) {
            float4 a0 = *(const float4*)(&As[kk][ty * 8]);
            float4 a1 = *(const float4*)(&As[kk][ty * 8 + 4]);
            float av[8] = {a0.x, a0.y, a0.z, a0.w, a1.x, a1.y, a1.z, a1.w};
            float bv[TN];
#pragma unroll
            for (int j = 0; j < TN; j++) bv[j] = Bs[kk][tx * TN + j];
#pragma unroll
            for (int i = 0; i < 8; i++)
#pragma unroll
                for (int j = 0; j < TN; j++) acc[i][j] += av[i] * bv[j];
        }
        __syncthreads();
    }
#pragma unroll
    for (int i = 0; i < 8; i++) {
        int gm = bm + ty * 8 + i;
        if (gm >= M) continue;
#pragma unroll
        for (int j = 0; j < TN; j++) {
            int gc = bn + tx * TN + j;
            if (gc < Nc) C[(size_t)gm * Nc + gc] = acc[i][j];
        }
    }
}

// ---------------- build Bcat = [W | fold_src | fold_dst] ----------------
__global__ void k_prep_bcat(const float* __restrict__ W, const float* __restrict__ a_src,
                            const float* __restrict__ a_dst, float* __restrict__ Bcat, int K)
{
    int idx = blockIdx.x * blockDim.x + threadIdx.x;
    if (idx >= K * 80) return;
    int k = idx / 80;
    int c = idx % 80;
    if (c < 64) {
        Bcat[idx] = W[(size_t)k * 64 + c];
    } else {
        int j = c - 64;
        int h = j & 7;
        const float* a = (j < 8) ? a_src : a_dst;
        float sum = 0.f;
#pragma unroll
        for (int q = 0; q < 8; q++)
            sum += W[(size_t)k * 64 + h * 8 + q] * a[h * 8 + q];
        Bcat[idx] = sum;
    }
}

__global__ void k_fold(const float* __restrict__ W, const float* __restrict__ a_src,
                       const float* __restrict__ a_dst, float* __restrict__ Wf,
                       int K, int C)
{
    int idx = blockIdx.x * blockDim.x + threadIdx.x;
    if (idx >= K * 16) return;
    int k = idx >> 4;
    int j = idx & 15;
    int h = j & 7;
    const float* a = (j < 8) ? a_src : a_dst;
    float sum = 0.f;
    for (int c = 0; c < C; c++)
        sum += W[(size_t)k * 8 * C + h * C + c] * a[h * C + c];
    Wf[idx] = sum;
}

// W5 -> transposed block-diag bf16 hi/lo planes: Wt[c][kk], kk = h*64+k'
__global__ void k_wprep(const float* __restrict__ W5,
                        __nv_bfloat16* __restrict__ Wth, __nv_bfloat16* __restrict__ Wtl)
{
    int idx = blockIdx.x * blockDim.x + threadIdx.x;
    if (idx >= 40 * 512) return;
    int c  = idx / 512;
    int kk = idx % 512;
    int h  = kk >> 6;
    int k  = kk & 63;
    float w = W5[(size_t)k * 320 + h * 40 + c];
    __nv_bfloat16 hi = __float2bfloat16_rn(w);
    __nv_bfloat16 lo = __float2bfloat16_rn(w - __bfloat162float(hi));
    Wth[idx] = hi;
    Wtl[idx] = lo;
}

// ---------------- concat-layer aggregation: one pass, 2 edges/warp-iter -------
__global__ __launch_bounds__(256) void k_agg_cat(
    const float* __restrict__ hs, const int* __restrict__ rowptr,
    const int* __restrict__ colx, const float* __restrict__ bias,
    float* __restrict__ out, int n)
{
    int node = (blockIdx.x * blockDim.x + threadIdx.x) >> 5;
    if (node >= n) return;
    int lane = threadIdx.x & 31;
    int beg = rowptr[node], end = rowptr[node + 1];

    int sub = lane >> 4;
    int r   = lane & 15;
    int h   = r >> 1;
    int q   = r & 1;
    float sdv = __ldg(hs + (size_t)node * 80 + 72 + h);

    float4 acc = make_float4(0.f, 0.f, 0.f, 0.f);
    float d = 0.f;

    int e0 = beg;
    for (; e0 + 4 <= end; e0 += 4) {
        int siA = __ldg(colx + e0 + sub);
        int siB = __ldg(colx + e0 + 2 + sub);
        const float* rA = hs + (size_t)siA * 80;
        const float* rB = hs + (size_t)siB * 80;
        float sA = __ldg(rA + 64 + h);
        float sB = __ldg(rB + 64 + h);
        float4 vA = __ldg((const float4*)(rA + h * 8 + q * 4));
        float4 vB = __ldg((const float4*)(rB + h * 8 + q * 4));
        float aA = sA + sdv; aA = aA > 0.f ? aA : 0.2f * aA;
        float aB = sB + sdv; aB = aB > 0.f ? aB : 0.2f * aB;
        float eA = __expf(aA);
        float eB = __expf(aB);
        if (q == 0) d += eA + eB;
        acc.x += eA * vA.x + eB * vB.x;
        acc.y += eA * vA.y + eB * vB.y;
        acc.z += eA * vA.z + eB * vB.z;
        acc.w += eA * vA.w + eB * vB.w;
    }
    for (; e0 < end; e0 += 2) {
        int ee = e0 + sub;
        bool ok = ee < end;
        int si = ok ? __ldg(colx + ee) : node;
        const float* row = hs + (size_t)si * 80;
        float ssv = __ldg(row + 64 + h);
        float4 v  = __ldg((const float4*)(row + h * 8 + q * 4));
        float al = ssv + sdv; al = al > 0.f ? al : 0.2f * al;
        float ex = ok ? __expf(al) : 0.f;
        if (q == 0) d += ex;
        acc.x += ex * v.x;
        acc.y += ex * v.y;
        acc.z += ex * v.z;
        acc.w += ex * v.w;
    }

    acc.x += __shfl_xor_sync(0xffffffffu, acc.x, 16);
    acc.y += __shfl_xor_sync(0xffffffffu, acc.y, 16);
    acc.z += __shfl_xor_sync(0xffffffffu, acc.z, 16);
    acc.w += __shfl_xor_sync(0xffffffffu, acc.w, 16);
    d     += __shfl_xor_sync(0xffffffffu, d, 16);
    d     += __shfl_xor_sync(0xffffffffu, d, 1);

    if (sub == 0) {
        float inv = 1.f / (d + 1e-16f);
        int ch = h * 8 + q * 4;
        float4 b = __ldg((const float4*)(bias + ch));
        float4 rv;
        rv.x = acc.x * inv + b.x;
        rv.y = acc.y * inv + b.y;
        rv.z = acc.z * inv + b.z;
        rv.w = acc.w * inv + b.w;
        rv.x = rv.x > 0.f ? rv.x : 0.2f * rv.x;
        rv.y = rv.y > 0.f ? rv.y : 0.2f * rv.y;
        rv.z = rv.z > 0.f ? rv.z : 0.2f * rv.z;
        rv.w = rv.w > 0.f ? rv.w : 0.2f * rv.w;
        *(float4*)(out + (size_t)node * 64 + ch) = rv;
    }
}

// ---------------- layer-5 aggregation: y[N,8,64] -> bf16 hi/lo planes ---------
__global__ __launch_bounds__(256) void k_agg_mean(
    const float* __restrict__ xin, const float* __restrict__ s,
    const int* __restrict__ rowptr, const int* __restrict__ colx,
    __nv_bfloat16* __restrict__ yh, __nv_bfloat16* __restrict__ yl,
    float* __restrict__ exbuf, int n)
{
    int node = (blockIdx.x * blockDim.x + threadIdx.x) >> 5;
    if (node >= n) return;
    int lane = threadIdx.x & 31;
    int beg = rowptr[node], end = rowptr[node + 1];

    float sdv[8];
    const float* sd = s + (size_t)node * 16 + 8;
#pragma unroll
    for (int h = 0; h < 8; h++) sdv[h] = __ldg(sd + h);

    float dsum[8];
#pragma unroll
    for (int h = 0; h < 8; h++) dsum[h] = 0.f;

    for (int e = beg + lane; e < end; e += 32) {
        int si = colx[e];
        const float4* sp = (const float4*)(s + (size_t)si * 16);
        float4 s0 = __ldg(sp);
        float4 s1 = __ldg(sp + 1);
        float ss[8] = {s0.x, s0.y, s0.z, s0.w, s1.x, s1.y, s1.z, s1.w};
        float ex[8];
#pragma unroll
        for (int h = 0; h < 8; h++) {
            float al = ss[h] + sdv[h];
            al = al > 0.f ? al : 0.2f * al;
            ex[h] = __expf(al);
            dsum[h] += ex[h];
        }
        float4* ep = (float4*)(exbuf + (size_t)e * 8);
        ep[0] = make_float4(ex[0], ex[1], ex[2], ex[3]);
        ep[1] = make_float4(ex[4], ex[5], ex[6], ex[7]);
    }
#pragma unroll
    for (int off = 16; off; off >>= 1)
#pragma unroll
        for (int h = 0; h < 8; h++)
            dsum[h] += __shfl_xor_sync(0xffffffffu, dsum[h], off);

    float inv[8];
#pragma unroll
    for (int h = 0; h < 8; h++) inv[h] = 1.f / (dsum[h] + 1e-16f);
    __syncwarp();

    int sub = lane >> 4;
    int kb  = (lane & 15) * 4;

    float4 acc8[8];
#pragma unroll
    for (int h = 0; h < 8; h++) acc8[h] = make_float4(0.f, 0.f, 0.f, 0.f);

    int e0 = beg;
    for (; e0 + 2 <= end; e0 += 2) {
        int ee = e0 + sub;
        int si = __ldg(colx + ee);
        const float4* ap = (const float4*)(exbuf + (size_t)ee * 8);
        float4 q0 = __ldg(ap);
        float4 q1 = __ldg(ap + 1);
        float4 v  = __ldg((const float4*)(xin + (size_t)si * 64 + kb));
        float av[8] = {q0.x, q0.y, q0.z, q0.w, q1.x, q1.y, q1.z, q1.w};
#pragma unroll
        for (int h = 0; h < 8; h++) {
            acc8[h].x += av[h] * v.x;
            acc8[h].y += av[h] * v.y;
            acc8[h].z += av[h] * v.z;
            acc8[h].w += av[h] * v.w;
        }
    }
    if (e0 < end && sub == 0) {
        int si = __ldg(colx + e0);
        const float4* ap = (const float4*)(exbuf + (size_t)e0 * 8);
        float4 q0 = __ldg(ap);
        float4 q1 = __ldg(ap + 1);
        float4 v  = __ldg((const float4*)(xin + (size_t)si * 64 + kb));
        float av[8] = {q0.x, q0.y, q0.z, q0.w, q1.x, q1.y, q1.z, q1.w};
#pragma unroll
        for (int h = 0; h < 8; h++) {
            acc8[h].x += av[h] * v.x;
            acc8[h].y += av[h] * v.y;
            acc8[h].z += av[h] * v.z;
            acc8[h].w += av[h] * v.w;
        }
    }

#pragma unroll
    for (int h = 0; h < 8; h++) {
        acc8[h].x += __shfl_xor_sync(0xffffffffu, acc8[h].x, 16);
        acc8[h].y += __shfl_xor_sync(0xffffffffu, acc8[h].y, 16);
        acc8[h].z += __shfl_xor_sync(0xffffffffu, acc8[h].z, 16);
        acc8[h].w += __shfl_xor_sync(0xffffffffu, acc8[h].w, 16);
    }

    if (sub == 0) {
#pragma unroll
        for (int h = 0; h < 8; h++) {
            float w0 = acc8[h].x * inv[h];
            float w1 = acc8[h].y * inv[h];
            float w2 = acc8[h].z * inv[h];
            float w3 = acc8[h].w * inv[h];
            size_t o = (size_t)node * 512 + (size_t)h * 64 + kb;
            __nv_bfloat16 h0 = __float2bfloat16_rn(w0);
            __nv_bfloat16 h1 = __float2bfloat16_rn(w1);
            __nv_bfloat16 h2 = __float2bfloat16_rn(w2);
            __nv_bfloat16 h3 = __float2bfloat16_rn(w3);
            __nv_bfloat16 l0 = __float2bfloat16_rn(w0 - __bfloat162float(h0));
            __nv_bfloat16 l1 = __float2bfloat16_rn(w1 - __bfloat162float(h1));
            __nv_bfloat16 l2 = __float2bfloat16_rn(w2 - __bfloat162float(h2));
            __nv_bfloat16 l3 = __float2bfloat16_rn(w3 - __bfloat162float(h3));
            *(__nv_bfloat162*)(yh + o)     = __nv_bfloat162(h0, h1);
            *(__nv_bfloat162*)(yh + o + 2) = __nv_bfloat162(h2, h3);
            *(__nv_bfloat162*)(yl + o)     = __nv_bfloat162(l0, l1);
            *(__nv_bfloat162*)(yl + o + 2) = __nv_bfloat162(l2, l3);
        }
    }
}

// ---------------- final tensor-core GEMM + fused lsm ----------------
// pre[n,40] = (yh+yl)[n,512] @ (Wth+Wtl)^T via split-bf16 (3 mma), then
// mean(/8)+bias+log_softmax fused in the epilogue.
__global__ __launch_bounds__(128) void k_gemm_tc(
    const __nv_bfloat16* __restrict__ yh, const __nv_bfloat16* __restrict__ yl,
    const __nv_bfloat16* __restrict__ Wth, const __nv_bfloat16* __restrict__ Wtl,
    const float* __restrict__ b5, float* __restrict__ out, int n)
{
    __shared__ __nv_bfloat16 sAh[64 * 72];
    __shared__ __nv_bfloat16 sAl[64 * 72];
    __shared__ __nv_bfloat16 sBh[40 * 72];
    __shared__ __nv_bfloat16 sBl[40 * 72];

    int tid  = threadIdx.x;
    int bm   = blockIdx.x * 64;
    int wid  = tid >> 5;
    int lane = tid & 31;
    int g    = lane >> 2;          // fragment group row
    int t2   = (lane & 3) * 2;     // fragment col pair base
    int mw   = wid * 16;

    float c0[5], c1[5], c2[5], c3[5];
#pragma unroll
    for (int j = 0; j < 5; j++) { c0[j] = c1[j] = c2[j] = c3[j] = 0.f; }

    const uint32_t* yh32 = (const uint32_t*)yh;
    const uint32_t* yl32 = (const uint32_t*)yl;
    const uint32_t* wh32 = (const uint32_t*)Wth;
    const uint32_t* wl32 = (const uint32_t*)Wtl;

    for (int k0 = 0; k0 < 512; k0 += 64) {
        // load A chunk (64 rows x 64 cols) for both planes, as u32 (2 bf16)
#pragma unroll
        for (int i = 0; i < 16; i++) {
            int idx = tid + i * 128;              // 0..2047
            int row = idx >> 5;
            int cu  = idx & 31;
            int gr  = bm + row;
            uint32_t vh = 0, vl = 0;
            if (gr < n) {
                size_t off = (size_t)gr * 256 + (k0 >> 1) + cu;
                vh = yh32[off];
                vl = yl32[off];
            }
            *(uint32_t*)(&sAh[row * 72 + cu * 2]) = vh;
            *(uint32_t*)(&sAl[row * 72 + cu * 2]) = vl;
        }
        // load B chunk (40 rows x 64 cols)
#pragma unroll
        for (int i = 0; i < 10; i++) {
            int idx = tid + i * 128;              // 0..1279
            int c  = idx >> 5;
            int cu = idx & 31;
            size_t off = (size_t)c * 256 + (k0 >> 1) + cu;
            *(uint32_t*)(&sBh[c * 72 + cu * 2]) = wh32[off];
            *(uint32_t*)(&sBl[c * 72 + cu * 2]) = wl32[off];
        }
        __syncthreads();

#pragma unroll
        for (int ks = 0; ks < 64; ks += 16) {
            int arow0 = (mw + g) * 72 + ks + t2;
            int arow1 = (mw + g + 8) * 72 + ks + t2;
            uint32_t a0h = *(const uint32_t*)(&sAh[arow0]);
            uint32_t a1h = *(const uint32_t*)(&sAh[arow1]);
            uint32_t a2h = *(const uint32_t*)(&sAh[arow0 + 8]);
            uint32_t a3h = *(const uint32_t*)(&sAh[arow1 + 8]);
            uint32_t a0l = *(const uint32_t*)(&sAl[arow0]);
            uint32_t a1l = *(const uint32_t*)(&sAl[arow1]);
            uint32_t a2l = *(const uint32_t*)(&sAl[arow0 + 8]);
            uint32_t a3l = *(const uint32_t*)(&sAl[arow1 + 8]);
#pragma unroll
            for (int j = 0; j < 5; j++) {
                int brow = (j * 8 + g) * 72 + ks + t2;
                uint32_t b0h = *(const uint32_t*)(&sBh[brow]);
                uint32_t b1h = *(const uint32_t*)(&sBh[brow + 8]);
                uint32_t b0l = *(const uint32_t*)(&sBl[brow]);
                uint32_t b1l = *(const uint32_t*)(&sBl[brow + 8]);
                asm volatile(
                    "mma.sync.aligned.m16n8k16.row.col.f32.bf16.bf16.f32 "
                    "{%0,%1,%2,%3}, {%4,%5,%6,%7}, {%8,%9}, {%0,%1,%2,%3};"
                    : "+f"(c0[j]), "+f"(c1[j]), "+f"(c2[j]), "+f"(c3[j])
                    : "r"(a0h), "r"(a1h), "r"(a2h), "r"(a3h), "r"(b0h), "r"(b1h));
                asm volatile(
                    "mma.sync.aligned.m16n8k16.row.col.f32.bf16.bf16.f32 "
                    "{%0,%1,%2,%3}, {%4,%5,%6,%7}, {%8,%9}, {%0,%1,%2,%3};"
                    : "+f"(c0[j]), "+f"(c1[j]), "+f"(c2[j]), "+f"(c3[j])
                    : "r"(a0h), "r"(a1h), "r"(a2h), "r"(a3h), "r"(b0l), "r"(b1l));
                asm volatile(
                    "mma.sync.aligned.m16n8k16.row.col.f32.bf16.bf16.f32 "
                    "{%0,%1,%2,%3}, {%4,%5,%6,%7}, {%8,%9}, {%0,%1,%2,%3};"
                    : "+f"(c0[j]), "+f"(c1[j]), "+f"(c2[j]), "+f"(c3[j])
                    : "r"(a0l), "r"(a1l), "r"(a2l), "r"(a3l), "r"(b0h), "r"(b1h));
            }
        }
        __syncthreads();
    }

    // epilogue: rows r0 = bm+mw+g, r1 = r0+8; cols j*8+t2, +1
    int row0 = bm + mw + g;
    int row1 = row0 + 8;
    float v0[5], w0[5], v1[5], w1[5];
#pragma unroll
    for (int j = 0; j < 5; j++) {
        float2 b = *(const float2*)(b5 + j * 8 + t2);
        v0[j] = c0[j] * 0.125f + b.x;
        w0[j] = c1[j] * 0.125f + b.y;
        v1[j] = c2[j] * 0.125f + b.x;
        w1[j] = c3[j] * 0.125f + b.y;
    }
    float m0 = -1e30f, m1 = -1e30f;
#pragma unroll
    for (int j = 0; j < 5; j++) {
        m0 = fmaxf(m0, fmaxf(v0[j], w0[j]));
        m1 = fmaxf(m1, fmaxf(v1[j], w1[j]));
    }
    m0 = fmaxf(m0, __shfl_xor_sync(0xffffffffu, m0, 1));
    m0 = fmaxf(m0, __shfl_xor_sync(0xffffffffu, m0, 2));
    m1 = fmaxf(m1, __shfl_xor_sync(0xffffffffu, m1, 1));
    m1 = fmaxf(m1, __shfl_xor_sync(0xffffffffu, m1, 2));
    float s0 = 0.f, s1 = 0.f;
#pragma unroll
    for (int j = 0; j < 5; j++) {
        s0 += __expf(v0[j] - m0) + __expf(w0[j] - m0);
        s1 += __expf(v1[j] - m1) + __expf(w1[j] - m1);
    }
    s0 += __shfl_xor_sync(0xffffffffu, s0, 1);
    s0 += __shfl_xor_sync(0xffffffffu, s0, 2);
    s1 += __shfl_xor_sync(0xffffffffu, s1, 1);
    s1 += __shfl_xor_sync(0xffffffffu, s1, 2);
    float lse0 = m0 + __logf(s0);
    float lse1 = m1 + __logf(s1);

    if (row0 < n) {
#pragma unroll
        for (int j = 0; j < 5; j++)
            *(float2*)(out + (size_t)row0 * 40 + j * 8 + t2) =
                make_float2(v0[j] - lse0, w0[j] - lse0);
    }
    if (row1 < n) {
#pragma unroll
        for (int j = 0; j < 5; j++)
            *(float2*)(out + (size_t)row1 * 40 + j * 8 + t2) =
                make_float2(v1[j] - lse1, w1[j] - lse1);
    }
}

// ---------------- host ----------------
static void* sym(const void* s) {
    void* p = nullptr;
    cudaGetSymbolAddress(&p, s);
    return p;
}

extern "C" void kernel_launch(void* const* d_in, const int* in_sizes, int n_in,
                              void* d_out, int out_size)
{
    const float* x   = (const float*)d_in[0];
    const int*   ei  = (const int*)d_in[1];
    const float* Ws[5]  = {(const float*)d_in[2],  (const float*)d_in[6],
                           (const float*)d_in[10], (const float*)d_in[14],
                           (const float*)d_in[18]};
    const float* asv[5] = {(const float*)d_in[3],  (const float*)d_in[7],
                           (const float*)d_in[11], (const float*)d_in[15],
                           (const float*)d_in[19]};
    const float* adv[5] = {(const float*)d_in[4],  (const float*)d_in[8],
                           (const float*)d_in[12], (const float*)d_in[16],
                           (const float*)d_in[20]};
    const float* bs[5]  = {(const float*)d_in[5],  (const float*)d_in[9],
                           (const float*)d_in[13], (const float*)d_in[17],
                           (const float*)d_in[21]};

    int n = in_sizes[0] / 128;
    int E = in_sizes[1] / 2;

    float* hs     = (float*)sym(g_hs);
    float* actA   = (float*)sym(g_actA);
    float* actB   = (float*)sym(g_actB);
    float* sbuf   = (float*)sym(g_sbuf);
    float* exbuf  = (float*)sym(g_ex);
    int*   col    = (int*)  sym(g_col);
    int*   rowptr = (int*)  sym(g_rowptr);
    int*   cursor = (int*)  sym(g_cursor);
    int*   cnt    = (int*)  sym(g_cnt);
    int*   bsum   = (int*)  sym(g_bsum);
    __nv_bfloat16* yh  = (__nv_bfloat16*)sym(g_yh);
    __nv_bfloat16* yl  = (__nv_bfloat16*)sym(g_yl);
    __nv_bfloat16* Wth = (__nv_bfloat16*)sym(g_Wth);
    __nv_bfloat16* Wtl = (__nv_bfloat16*)sym(g_Wtl);
    float* Bcat   = (float*)sym(g_Bcat);
    float* Wfold  = (float*)sym(g_Wfold);

    // ---- CSR build (dst-grouped) ----
    int nb = (n + 1023) / 1024;
    k_init_cnt<<<(n + 255) / 256, 256>>>(cnt, n);
    k_hist<<<(E + 255) / 256, 256>>>(ei + E, cnt, E);
    k_scan1<<<nb, 1024>>>(cnt, rowptr, bsum, n);
    k_scan2<<<1, 64>>>(bsum, nb);
    k_scan3<<<(n + 255) / 256, 256>>>(rowptr, cursor, bsum, cnt, n);
    k_scatter<<<(E + n + 255) / 256, 256>>>(ei, cursor, col, E, n);

    int warpBlocks = (n + 7) / 8;
    int rowGrid = (n + 127) / 128;

    // ---- layers 1..4: fused [h|s] GEMM + one-pass aggregate ----
    const float* cur = x;
    int K = 128;
    float* acts[2] = {actA, actB};
    for (int L = 0; L < 4; L++) {
        k_prep_bcat<<<(K * 80 + 255) / 256, 256>>>(Ws[L], asv[L], adv[L], Bcat, K);
        {
            dim3 g(1, rowGrid);
            k_gemm<5><<<g, 256>>>(cur, Bcat, hs, n, 80, K);
        }
        k_agg_cat<<<warpBlocks, 256>>>(hs, rowptr, col, bs[L], acts[L & 1], n);
        cur = acts[L & 1];
        K = 64;
    }

    // ---- layer 5: aggregate x4 per head (bf16 split), tensor GEMM + lsm ----
    k_fold<<<(64 * 16 + 255) / 256, 256>>>(Ws[4], asv[4], adv[4], Wfold, 64, 40);
    {
        dim3 g(1, rowGrid);
        k_gemm<1><<<g, 256>>>(cur, Wfold, sbuf, n, 16, 64);
    }
    k_agg_mean<<<warpBlocks, 256>>>(cur, sbuf, rowptr, col, yh, yl, exbuf, n);
    k_wprep<<<(40 * 512 + 255) / 256, 256>>>(Ws[4], Wth, Wtl);
    k_gemm_tc<<<(n + 63) / 64, 128>>>(yh, yl, Wth, Wtl, bs[4], (float*)d_out, n);
}

// round 8
// speedup vs baseline: 3.2424x; 1.0996x over previous
#include <cuda_runtime.h>
#include <cuda_bf16.h>
#include <cstddef>
#include <cstdint>

// Problem constants: N=50000, F=128, H=8, HID=8, CLS=40, E=1.6M
#define NMAX 50000
#define EMAX 1700000

// ---------------- static device scratch ----------------
__device__ float g_hs   [(size_t)NMAX * 96];   // stride 96 (=384B aligned): [0..63]=h, [64..71]=s_src, [72..79]=s_dst
__device__ float g_act  [(size_t)NMAX * 64];   // fp32 activation (only layer-4 output used)
__device__ __nv_bfloat16 g_xh[(size_t)NMAX * 128];
__device__ __nv_bfloat16 g_xl[(size_t)NMAX * 128];
__device__ __nv_bfloat16 g_ah[(size_t)NMAX * 64];
__device__ __nv_bfloat16 g_al[(size_t)NMAX * 64];
__device__ float g_sbuf [(size_t)NMAX * 16];
__device__ float g_ex   [(size_t)EMAX * 8];
__device__ int   g_col  [EMAX];
__device__ int   g_rowptr[NMAX + 1];
__device__ int   g_cursor[NMAX];
__device__ int   g_cnt   [NMAX];
__device__ int   g_bsum [64];
__device__ __nv_bfloat16 g_yh[(size_t)NMAX * 512];
__device__ __nv_bfloat16 g_yl[(size_t)NMAX * 512];
__device__ __nv_bfloat16 g_Wth[40 * 512];
__device__ __nv_bfloat16 g_Wtl[40 * 512];
__device__ __nv_bfloat16 g_Bth[80 * 128];      // Bcat^T hi plane [80][K]
__device__ __nv_bfloat16 g_Btl[80 * 128];
__device__ float g_Wfold[128 * 16];

// ---------------- CSR build ----------------
__global__ void k_init_cnt(int* cnt, int n) {
    int i = blockIdx.x * blockDim.x + threadIdx.x;
    if (i < n) cnt[i] = 1;
}

__global__ void k_hist(const int* __restrict__ dst, int* cnt, int E) {
    int i = blockIdx.x * blockDim.x + threadIdx.x;
    if (i < E) atomicAdd(&cnt[dst[i]], 1);
}

__global__ void k_scan1(const int* __restrict__ cnt, int* rowptr, int* bsum, int n) {
    __shared__ int sm[1024];
    int tid = threadIdx.x;
    int i = blockIdx.x * 1024 + tid;
    int v = (i < n) ? cnt[i] : 0;
    sm[tid] = v;
    __syncthreads();
    for (int off = 1; off < 1024; off <<= 1) {
        int t = (tid >= off) ? sm[tid - off] : 0;
        __syncthreads();
        sm[tid] += t;
        __syncthreads();
    }
    if (i < n) rowptr[i] = sm[tid] - v;
    if (tid == 1023) bsum[blockIdx.x] = sm[1023];
}

__global__ void k_scan2(int* bsum, int nb) {
    __shared__ int sm[64];
    int tid = threadIdx.x;
    sm[tid] = (tid < nb) ? bsum[tid] : 0;
    __syncthreads();
    if (tid == 0) {
        int run = 0;
        for (int j = 0; j < nb; j++) { int t = sm[j]; sm[j] = run; run += t; }
    }
    __syncthreads();
    if (tid < nb) bsum[tid] = sm[tid];
}

__global__ void k_scan3(int* rowptr, int* cursor, const int* __restrict__ bsum,
                        const int* __restrict__ cnt, int n) {
    int i = blockIdx.x * blockDim.x + threadIdx.x;
    if (i < n) {
        int v = rowptr[i] + bsum[i >> 10];
        rowptr[i] = v;
        cursor[i] = v;
        if (i == n - 1) rowptr[n] = v + cnt[i];
    }
}

__global__ void k_scatter(const int* __restrict__ ei, int* cursor, int* col, int E, int n) {
    int i = blockIdx.x * blockDim.x + threadIdx.x;
    if (i < E) {
        int s = ei[i];
        int d = ei[E + i];
        int p = atomicAdd(&cursor[d], 1);
        col[p] = s;
    } else if (i < E + n) {
        int nd = i - E;
        int p = atomicAdd(&cursor[nd], 1);
        col[p] = nd;
    }
}

// ---------------- split fp32 -> bf16 hi/lo planes ----------------
__global__ void k_split(const float* __restrict__ A, __nv_bfloat16* __restrict__ Ah,
                        __nv_bfloat16* __restrict__ Al, int sz)
{
    int i = blockIdx.x * blockDim.x + threadIdx.x;
    if (i < sz) {
        float v = A[i];
        __nv_bfloat16 hi = __float2bfloat16_rn(v);
        Ah[i] = hi;
        Al[i] = __float2bfloat16_rn(v - __bfloat162float(hi));
    }
}

// ---------------- small fp32 SGEMM (layer-5 scores): C[M,16] = A[M,64]@B[64,16] --
template<int TN>
__global__ __launch_bounds__(256) void k_gemm(
    const float* __restrict__ A, const float* __restrict__ B, float* __restrict__ C,
    int M, int Nc, int K)
{
    const int BN = 16 * TN;
    __shared__ float As[16][132];
    __shared__ float Bs[16][BN];
    int tid = threadIdx.x;
    int bm = blockIdx.y * 128;
    int bn = blockIdx.x * BN;
    int tx = tid & 15;
    int ty = tid >> 4;
    float acc[8][TN];
#pragma unroll
    for (int i = 0; i < 8; i++)
#pragma unroll
        for (int j = 0; j < TN; j++) acc[i][j] = 0.f;

    for (int k0 = 0; k0 < K; k0 += 16) {
#pragma unroll
        for (int it = 0; it < 2; it++) {
            int idx = tid + it * 256;
            int m  = idx >> 2;
            int kq = (idx & 3) * 4;
            int gm = bm + m;
            float4 v = make_float4(0.f, 0.f, 0.f, 0.f);
            if (gm < M) v = *(const float4*)(A + (size_t)gm * K + k0 + kq);
            As[kq + 0][m] = v.x;
            As[kq + 1][m] = v.y;
            As[kq + 2][m] = v.z;
            As[kq + 3][m] = v.w;
        }
        for (int idx = tid; idx < 16 * BN; idx += 256) {
            int kk = idx / BN;
            int cc = idx % BN;
            int gc = bn + cc;
            float v = 0.f;
            if (gc < Nc) v = B[(size_t)(k0 + kk) * Nc + gc];
            Bs[kk][cc] = v;
        }
        __syncthreads();
#pragma unroll
        for (int kk = 0; kk < 16; kk++) {
            float4 a0 = *(const float4*)(&As[kk][ty * 8]);
            float4 a1 = *(const float4*)(&As[kk][ty * 8 + 4]);
            float av[8] = {a0.x, a0.y, a0.z, a0.w, a1.x, a1.y, a1.z, a1.w};
            float bv[TN];
#pragma unroll
            for (int j = 0; j < TN; j++) bv[j] = Bs[kk][tx * TN + j];
#pragma unroll
            for (int i = 0; i < 8; i++)
#pragma unroll
                for (int j = 0; j < TN; j++) acc[i][j] += av[i] * bv[j];
        }
        __syncthreads();
    }
#pragma unroll
    for (int i = 0; i < 8; i++) {
        int gm = bm + ty * 8 + i;
        if (gm >= M) continue;
#pragma unroll
        for (int j = 0; j < TN; j++) {
            int gc = bn + tx * TN + j;
            if (gc < Nc) C[(size_t)gm * Nc + gc] = acc[i][j];
        }
    }
}

// ---------------- BcatT = [W | fold_src | fold_dst]^T as split planes [80][K] ----
__global__ void k_prep_bcat_t(const float* __restrict__ W, const float* __restrict__ a_src,
                              const float* __restrict__ a_dst,
                              __nv_bfloat16* __restrict__ Bth, __nv_bfloat16* __restrict__ Btl,
                              int K)
{
    int idx = blockIdx.x * blockDim.x + threadIdx.x;
    if (idx >= 80 * K) return;
    int c = idx / K;
    int k = idx % K;
    float val;
    if (c < 64) {
        val = W[(size_t)k * 64 + c];
    } else {
        int j = c - 64;
        int h = j & 7;
        const float* a = (j < 8) ? a_src : a_dst;
        float sum = 0.f;
#pragma unroll
        for (int q = 0; q < 8; q++)
            sum += W[(size_t)k * 64 + h * 8 + q] * a[h * 8 + q];
        val = sum;
    }
    __nv_bfloat16 hi = __float2bfloat16_rn(val);
    Bth[idx] = hi;
    Btl[idx] = __float2bfloat16_rn(val - __bfloat162float(hi));
}

__global__ void k_fold(const float* __restrict__ W, const float* __restrict__ a_src,
                       const float* __restrict__ a_dst, float* __restrict__ Wf,
                       int K, int C)
{
    int idx = blockIdx.x * blockDim.x + threadIdx.x;
    if (idx >= K * 16) return;
    int k = idx >> 4;
    int j = idx & 15;
    int h = j & 7;
    const float* a = (j < 8) ? a_src : a_dst;
    float sum = 0.f;
    for (int c = 0; c < C; c++)
        sum += W[(size_t)k * 8 * C + h * C + c] * a[h * C + c];
    Wf[idx] = sum;
}

__global__ void k_wprep(const float* __restrict__ W5,
                        __nv_bfloat16* __restrict__ Wth, __nv_bfloat16* __restrict__ Wtl)
{
    int idx = blockIdx.x * blockDim.x + threadIdx.x;
    if (idx >= 40 * 512) return;
    int c  = idx / 512;
    int kk = idx % 512;
    int h  = kk >> 6;
    int k  = kk & 63;
    float w = W5[(size_t)k * 320 + h * 40 + c];
    __nv_bfloat16 hi = __float2bfloat16_rn(w);
    Wth[idx] = hi;
    Wtl[idx] = __float2bfloat16_rn(w - __bfloat162float(hi));
}

// ---------------- layers 1-4 fused GEMM on tensor cores ----------------
// hs[n,96(stride)] cols 0..79 = A[n,K](split planes) @ BcatT^T; 3-mma split-bf16.
__global__ __launch_bounds__(128) void k_gemm80_tc(
    const __nv_bfloat16* __restrict__ Ah, const __nv_bfloat16* __restrict__ Al,
    const __nv_bfloat16* __restrict__ Bth, const __nv_bfloat16* __restrict__ Btl,
    float* __restrict__ C, int n, int K)
{
    __shared__ __nv_bfloat16 sAh[64 * 72];
    __shared__ __nv_bfloat16 sAl[64 * 72];
    __shared__ __nv_bfloat16 sBh[80 * 72];
    __shared__ __nv_bfloat16 sBl[80 * 72];

    int tid  = threadIdx.x;
    int bm   = blockIdx.x * 64;
    int wid  = tid >> 5;
    int lane = tid & 31;
    int g    = lane >> 2;
    int t2   = (lane & 3) * 2;
    int mw   = wid * 16;
    int Ku   = K >> 1;                 // row width in u32

    float c0[10], c1[10], c2[10], c3[10];
#pragma unroll
    for (int j = 0; j < 10; j++) { c0[j] = c1[j] = c2[j] = c3[j] = 0.f; }

    const uint32_t* ah32 = (const uint32_t*)Ah;
    const uint32_t* al32 = (const uint32_t*)Al;
    const uint32_t* bh32 = (const uint32_t*)Bth;
    const uint32_t* bl32 = (const uint32_t*)Btl;

    for (int k0 = 0; k0 < K; k0 += 64) {
#pragma unroll
        for (int i = 0; i < 16; i++) {
            int idx = tid + i * 128;
            int row = idx >> 5;
            int cu  = idx & 31;
            int gr  = bm + row;
            uint32_t vh = 0, vl = 0;
            if (gr < n) {
                size_t off = (size_t)gr * Ku + (k0 >> 1) + cu;
                vh = ah32[off];
                vl = al32[off];
            }
            *(uint32_t*)(&sAh[row * 72 + cu * 2]) = vh;
            *(uint32_t*)(&sAl[row * 72 + cu * 2]) = vl;
        }
#pragma unroll
        for (int i = 0; i < 20; i++) {
            int idx = tid + i * 128;
            int c  = idx >> 5;
            int cu = idx & 31;
            size_t off = (size_t)c * Ku + (k0 >> 1) + cu;
            *(uint32_t*)(&sBh[c * 72 + cu * 2]) = bh32[off];
            *(uint32_t*)(&sBl[c * 72 + cu * 2]) = bl32[off];
        }
        __syncthreads();

#pragma unroll
        for (int ks = 0; ks < 64; ks += 16) {
            int arow0 = (mw + g) * 72 + ks + t2;
            int arow1 = (mw + g + 8) * 72 + ks + t2;
            uint32_t a0h = *(const uint32_t*)(&sAh[arow0]);
            uint32_t a1h = *(const uint32_t*)(&sAh[arow1]);
            uint32_t a2h = *(const uint32_t*)(&sAh[arow0 + 8]);
            uint32_t a3h = *(const uint32_t*)(&sAh[arow1 + 8]);
            uint32_t a0l = *(const uint32_t*)(&sAl[arow0]);
            uint32_t a1l = *(const uint32_t*)(&sAl[arow1]);
            uint32_t a2l = *(const uint32_t*)(&sAl[arow0 + 8]);
            uint32_t a3l = *(const uint32_t*)(&sAl[arow1 + 8]);
#pragma unroll
            for (int j = 0; j < 10; j++) {
                int brow = (j * 8 + g) * 72 + ks + t2;
                uint32_t b0h = *(const uint32_t*)(&sBh[brow]);
                uint32_t b1h = *(const uint32_t*)(&sBh[brow + 8]);
                uint32_t b0l = *(const uint32_t*)(&sBl[brow]);
                uint32_t b1l = *(const uint32_t*)(&sBl[brow + 8]);
                asm volatile(
                    "mma.sync.aligned.m16n8k16.row.col.f32.bf16.bf16.f32 "
                    "{%0,%1,%2,%3}, {%4,%5,%6,%7}, {%8,%9}, {%0,%1,%2,%3};"
                    : "+f"(c0[j]), "+f"(c1[j]), "+f"(c2[j]), "+f"(c3[j])
                    : "r"(a0h), "r"(a1h), "r"(a2h), "r"(a3h), "r"(b0h), "r"(b1h));
                asm volatile(
                    "mma.sync.aligned.m16n8k16.row.col.f32.bf16.bf16.f32 "
                    "{%0,%1,%2,%3}, {%4,%5,%6,%7}, {%8,%9}, {%0,%1,%2,%3};"
                    : "+f"(c0[j]), "+f"(c1[j]), "+f"(c2[j]), "+f"(c3[j])
                    : "r"(a0h), "r"(a1h), "r"(a2h), "r"(a3h), "r"(b0l), "r"(b1l));
                asm volatile(
                    "mma.sync.aligned.m16n8k16.row.col.f32.bf16.bf16.f32 "
                    "{%0,%1,%2,%3}, {%4,%5,%6,%7}, {%8,%9}, {%0,%1,%2,%3};"
                    : "+f"(c0[j]), "+f"(c1[j]), "+f"(c2[j]), "+f"(c3[j])
                    : "r"(a0l), "r"(a1l), "r"(a2l), "r"(a3l), "r"(b0h), "r"(b1h));
            }
        }
        __syncthreads();
    }

    int row0 = bm + mw + g;
    int row1 = row0 + 8;
#pragma unroll
    for (int j = 0; j < 10; j++) {
        int cc = j * 8 + t2;
        if (row0 < n)
            *(float2*)(C + (size_t)row0 * 96 + cc) = make_float2(c0[j], c1[j]);
        if (row1 < n)
            *(float2*)(C + (size_t)row1 * 96 + cc) = make_float2(c2[j], c3[j]);
    }
}

// ---------------- concat-layer aggregation: one pass, stride-96 hs ------------
// Writes split-bf16 activation planes; optional fp32 copy (layer 4 only).
__global__ __launch_bounds__(256) void k_agg_cat(
    const float* __restrict__ hs, const int* __restrict__ rowptr,
    const int* __restrict__ colx, const float* __restrict__ bias,
    __nv_bfloat16* __restrict__ oh, __nv_bfloat16* __restrict__ ol,
    float* __restrict__ outf, int n)
{
    int node = (blockIdx.x * blockDim.x + threadIdx.x) >> 5;
    if (node >= n) return;
    int lane = threadIdx.x & 31;
    int beg = rowptr[node], end = rowptr[node + 1];

    int sub = lane >> 4;
    int r   = lane & 15;
    int h   = r >> 1;
    int q   = r & 1;
    float sdv = __ldg(hs + (size_t)node * 96 + 72 + h);

    float4 acc = make_float4(0.f, 0.f, 0.f, 0.f);
    float d = 0.f;

    int e0 = beg;
    for (; e0 + 4 <= end; e0 += 4) {
        int siA = __ldg(colx + e0 + sub);
        int siB = __ldg(colx + e0 + 2 + sub);
        const float* rA = hs + (size_t)siA * 96;
        const float* rB = hs + (size_t)siB * 96;
        float sA = __ldg(rA + 64 + h);
        float sB = __ldg(rB + 64 + h);
        float4 vA = __ldg((const float4*)(rA + h * 8 + q * 4));
        float4 vB = __ldg((const float4*)(rB + h * 8 + q * 4));
        float aA = sA + sdv; aA = aA > 0.f ? aA : 0.2f * aA;
        float aB = sB + sdv; aB = aB > 0.f ? aB : 0.2f * aB;
        float eA = __expf(aA);
        float eB = __expf(aB);
        if (q == 0) d += eA + eB;
        acc.x += eA * vA.x + eB * vB.x;
        acc.y += eA * vA.y + eB * vB.y;
        acc.z += eA * vA.z + eB * vB.z;
        acc.w += eA * vA.w + eB * vB.w;
    }
    for (; e0 < end; e0 += 2) {
        int ee = e0 + sub;
        bool ok = ee < end;
        int si = ok ? __ldg(colx + ee) : node;
        const float* row = hs + (size_t)si * 96;
        float ssv = __ldg(row + 64 + h);
        float4 v  = __ldg((const float4*)(row + h * 8 + q * 4));
        float al = ssv + sdv; al = al > 0.f ? al : 0.2f * al;
        float ex = ok ? __expf(al) : 0.f;
        if (q == 0) d += ex;
        acc.x += ex * v.x;
        acc.y += ex * v.y;
        acc.z += ex * v.z;
        acc.w += ex * v.w;
    }

    acc.x += __shfl_xor_sync(0xffffffffu, acc.x, 16);
    acc.y += __shfl_xor_sync(0xffffffffu, acc.y, 16);
    acc.z += __shfl_xor_sync(0xffffffffu, acc.z, 16);
    acc.w += __shfl_xor_sync(0xffffffffu, acc.w, 16);
    d     += __shfl_xor_sync(0xffffffffu, d, 16);
    d     += __shfl_xor_sync(0xffffffffu, d, 1);

    if (sub == 0) {
        float inv = 1.f / (d + 1e-16f);
        int ch = h * 8 + q * 4;
        float4 b = __ldg((const float4*)(bias + ch));
        float4 rv;
        rv.x = acc.x * inv + b.x;
        rv.y = acc.y * inv + b.y;
        rv.z = acc.z * inv + b.z;
        rv.w = acc.w * inv + b.w;
        rv.x = rv.x > 0.f ? rv.x : 0.2f * rv.x;
        rv.y = rv.y > 0.f ? rv.y : 0.2f * rv.y;
        rv.z = rv.z > 0.f ? rv.z : 0.2f * rv.z;
        rv.w = rv.w > 0.f ? rv.w : 0.2f * rv.w;
        size_t o = (size_t)node * 64 + ch;
        __nv_bfloat16 h0 = __float2bfloat16_rn(rv.x);
        __nv_bfloat16 h1 = __float2bfloat16_rn(rv.y);
        __nv_bfloat16 h2 = __float2bfloat16_rn(rv.z);
        __nv_bfloat16 h3 = __float2bfloat16_rn(rv.w);
        *(__nv_bfloat162*)(oh + o)     = __nv_bfloat162(h0, h1);
        *(__nv_bfloat162*)(oh + o + 2) = __nv_bfloat162(h2, h3);
        __nv_bfloat162 lo01, lo23;
        lo01.x = __float2bfloat16_rn(rv.x - __bfloat162float(h0));
        lo01.y = __float2bfloat16_rn(rv.y - __bfloat162float(h1));
        lo23.x = __float2bfloat16_rn(rv.z - __bfloat162float(h2));
        lo23.y = __float2bfloat16_rn(rv.w - __bfloat162float(h3));
        *(__nv_bfloat162*)(ol + o)     = lo01;
        *(__nv_bfloat162*)(ol + o + 2) = lo23;
        if (outf) *(float4*)(outf + o) = rv;
    }
}

// ---------------- layer-5 aggregation: y[N,8,64] -> bf16 hi/lo planes ---------
__global__ __launch_bounds__(256) void k_agg_mean(
    const float* __restrict__ xin, const float* __restrict__ s,
    const int* __restrict__ rowptr, const int* __restrict__ colx,
    __nv_bfloat16* __restrict__ yh, __nv_bfloat16* __restrict__ yl,
    float* __restrict__ exbuf, int n)
{
    int node = (blockIdx.x * blockDim.x + threadIdx.x) >> 5;
    if (node >= n) return;
    int lane = threadIdx.x & 31;
    int beg = rowptr[node], end = rowptr[node + 1];

    float sdv[8];
    const float* sd = s + (size_t)node * 16 + 8;
#pragma unroll
    for (int h = 0; h < 8; h++) sdv[h] = __ldg(sd + h);

    float dsum[8];
#pragma unroll
    for (int h = 0; h < 8; h++) dsum[h] = 0.f;

    for (int e = beg + lane; e < end; e += 32) {
        int si = colx[e];
        const float4* sp = (const float4*)(s + (size_t)si * 16);
        float4 s0 = __ldg(sp);
        float4 s1 = __ldg(sp + 1);
        float ss[8] = {s0.x, s0.y, s0.z, s0.w, s1.x, s1.y, s1.z, s1.w};
        float ex[8];
#pragma unroll
        for (int h = 0; h < 8; h++) {
            float al = ss[h] + sdv[h];
            al = al > 0.f ? al : 0.2f * al;
            ex[h] = __expf(al);
            dsum[h] += ex[h];
        }
        float4* ep = (float4*)(exbuf + (size_t)e * 8);
        ep[0] = make_float4(ex[0], ex[1], ex[2], ex[3]);
        ep[1] = make_float4(ex[4], ex[5], ex[6], ex[7]);
    }
#pragma unroll
    for (int off = 16; off; off >>= 1)
#pragma unroll
        for (int h = 0; h < 8; h++)
            dsum[h] += __shfl_xor_sync(0xffffffffu, dsum[h], off);

    float inv[8];
#pragma unroll
    for (int h = 0; h < 8; h++) inv[h] = 1.f / (dsum[h] + 1e-16f);
    __syncwarp();

    int sub = lane >> 4;
    int kb  = (lane & 15) * 4;

    float4 acc8[8];
#pragma unroll
    for (int h = 0; h < 8; h++) acc8[h] = make_float4(0.f, 0.f, 0.f, 0.f);

    int e0 = beg;
    for (; e0 + 2 <= end; e0 += 2) {
        int ee = e0 + sub;
        int si = __ldg(colx + ee);
        const float4* ap = (const float4*)(exbuf + (size_t)ee * 8);
        float4 q0 = __ldg(ap);
        float4 q1 = __ldg(ap + 1);
        float4 v  = __ldg((const float4*)(xin + (size_t)si * 64 + kb));
        float av[8] = {q0.x, q0.y, q0.z, q0.w, q1.x, q1.y, q1.z, q1.w};
#pragma unroll
        for (int h = 0; h < 8; h++) {
            acc8[h].x += av[h] * v.x;
            acc8[h].y += av[h] * v.y;
            acc8[h].z += av[h] * v.z;
            acc8[h].w += av[h] * v.w;
        }
    }
    if (e0 < end && sub == 0) {
        int si = __ldg(colx + e0);
        const float4* ap = (const float4*)(exbuf + (size_t)e0 * 8);
        float4 q0 = __ldg(ap);
        float4 q1 = __ldg(ap + 1);
        float4 v  = __ldg((const float4*)(xin + (size_t)si * 64 + kb));
        float av[8] = {q0.x, q0.y, q0.z, q0.w, q1.x, q1.y, q1.z, q1.w};
#pragma unroll
        for (int h = 0; h < 8; h++) {
            acc8[h].x += av[h] * v.x;
            acc8[h].y += av[h] * v.y;
            acc8[h].z += av[h] * v.z;
            acc8[h].w += av[h] * v.w;
        }
    }

#pragma unroll
    for (int h = 0; h < 8; h++) {
        acc8[h].x += __shfl_xor_sync(0xffffffffu, acc8[h].x, 16);
        acc8[h].y += __shfl_xor_sync(0xffffffffu, acc8[h].y, 16);
        acc8[h].z += __shfl_xor_sync(0xffffffffu, acc8[h].z, 16);
        acc8[h].w += __shfl_xor_sync(0xffffffffu, acc8[h].w, 16);
    }

    if (sub == 0) {
#pragma unroll
        for (int h = 0; h < 8; h++) {
            float w0 = acc8[h].x * inv[h];
            float w1 = acc8[h].y * inv[h];
            float w2 = acc8[h].z * inv[h];
            float w3 = acc8[h].w * inv[h];
            size_t o = (size_t)node * 512 + (size_t)h * 64 + kb;
            __nv_bfloat16 h0 = __float2bfloat16_rn(w0);
            __nv_bfloat16 h1 = __float2bfloat16_rn(w1);
            __nv_bfloat16 h2 = __float2bfloat16_rn(w2);
            __nv_bfloat16 h3 = __float2bfloat16_rn(w3);
            *(__nv_bfloat162*)(yh + o)     = __nv_bfloat162(h0, h1);
            *(__nv_bfloat162*)(yh + o + 2) = __nv_bfloat162(h2, h3);
            __nv_bfloat162 l01, l23;
            l01.x = __float2bfloat16_rn(w0 - __bfloat162float(h0));
            l01.y = __float2bfloat16_rn(w1 - __bfloat162float(h1));
            l23.x = __float2bfloat16_rn(w2 - __bfloat162float(h2));
            l23.y = __float2bfloat16_rn(w3 - __bfloat162float(h3));
            *(__nv_bfloat162*)(yl + o)     = l01;
            *(__nv_bfloat162*)(yl + o + 2) = l23;
        }
    }
}

// ---------------- final tensor-core GEMM + fused lsm (unchanged from R7) ------
__global__ __launch_bounds__(128) void k_gemm_tc(
    const __nv_bfloat16* __restrict__ yh, const __nv_bfloat16* __restrict__ yl,
    const __nv_bfloat16* __restrict__ Wth, const __nv_bfloat16* __restrict__ Wtl,
    const float* __restrict__ b5, float* __restrict__ out, int n)
{
    __shared__ __nv_bfloat16 sAh[64 * 72];
    __shared__ __nv_bfloat16 sAl[64 * 72];
    __shared__ __nv_bfloat16 sBh[40 * 72];
    __shared__ __nv_bfloat16 sBl[40 * 72];

    int tid  = threadIdx.x;
    int bm   = blockIdx.x * 64;
    int wid  = tid >> 5;
    int lane = tid & 31;
    int g    = lane >> 2;
    int t2   = (lane & 3) * 2;
    int mw   = wid * 16;

    float c0[5], c1[5], c2[5], c3[5];
#pragma unroll
    for (int j = 0; j < 5; j++) { c0[j] = c1[j] = c2[j] = c3[j] = 0.f; }

    const uint32_t* yh32 = (const uint32_t*)yh;
    const uint32_t* yl32 = (const uint32_t*)yl;
    const uint32_t* wh32 = (const uint32_t*)Wth;
    const uint32_t* wl32 = (const uint32_t*)Wtl;

    for (int k0 = 0; k0 < 512; k0 += 64) {
#pragma unroll
        for (int i = 0; i < 16; i++) {
            int idx = tid + i * 128;
            int row = idx >> 5;
            int cu  = idx & 31;
            int gr  = bm + row;
            uint32_t vh = 0, vl = 0;
            if (gr < n) {
                size_t off = (size_t)gr * 256 + (k0 >> 1) + cu;
                vh = yh32[off];
                vl = yl32[off];
            }
            *(uint32_t*)(&sAh[row * 72 + cu * 2]) = vh;
            *(uint32_t*)(&sAl[row * 72 + cu * 2]) = vl;
        }
#pragma unroll
        for (int i = 0; i < 10; i++) {
            int idx = tid + i * 128;
            int c  = idx >> 5;
            int cu = idx & 31;
            size_t off = (size_t)c * 256 + (k0 >> 1) + cu;
            *(uint32_t*)(&sBh[c * 72 + cu * 2]) = wh32[off];
            *(uint32_t*)(&sBl[c * 72 + cu * 2]) = wl32[off];
        }
        __syncthreads();

#pragma unroll
        for (int ks = 0; ks < 64; ks += 16) {
            int arow0 = (mw + g) * 72 + ks + t2;
            int arow1 = (mw + g + 8) * 72 + ks + t2;
            uint32_t a0h = *(const uint32_t*)(&sAh[arow0]);
            uint32_t a1h = *(const uint32_t*)(&sAh[arow1]);
            uint32_t a2h = *(const uint32_t*)(&sAh[arow0 + 8]);
            uint32_t a3h = *(const uint32_t*)(&sAh[arow1 + 8]);
            uint32_t a0l = *(const uint32_t*)(&sAl[arow0]);
            uint32_t a1l = *(const uint32_t*)(&sAl[arow1]);
            uint32_t a2l = *(const uint32_t*)(&sAl[arow0 + 8]);
            uint32_t a3l = *(const uint32_t*)(&sAl[arow1 + 8]);
#pragma unroll
            for (int j = 0; j < 5; j++) {
                int brow = (j * 8 + g) * 72 + ks + t2;
                uint32_t b0h = *(const uint32_t*)(&sBh[brow]);
                uint32_t b1h = *(const uint32_t*)(&sBh[brow + 8]);
                uint32_t b0l = *(const uint32_t*)(&sBl[brow]);
                uint32_t b1l = *(const uint32_t*)(&sBl[brow + 8]);
                asm volatile(
                    "mma.sync.aligned.m16n8k16.row.col.f32.bf16.bf16.f32 "
                    "{%0,%1,%2,%3}, {%4,%5,%6,%7}, {%8,%9}, {%0,%1,%2,%3};"
                    : "+f"(c0[j]), "+f"(c1[j]), "+f"(c2[j]), "+f"(c3[j])
                    : "r"(a0h), "r"(a1h), "r"(a2h), "r"(a3h), "r"(b0h), "r"(b1h));
                asm volatile(
                    "mma.sync.aligned.m16n8k16.row.col.f32.bf16.bf16.f32 "
                    "{%0,%1,%2,%3}, {%4,%5,%6,%7}, {%8,%9}, {%0,%1,%2,%3};"
                    : "+f"(c0[j]), "+f"(c1[j]), "+f"(c2[j]), "+f"(c3[j])
                    : "r"(a0h), "r"(a1h), "r"(a2h), "r"(a3h), "r"(b0l), "r"(b1l));
                asm volatile(
                    "mma.sync.aligned.m16n8k16.row.col.f32.bf16.bf16.f32 "
                    "{%0,%1,%2,%3}, {%4,%5,%6,%7}, {%8,%9}, {%0,%1,%2,%3};"
                    : "+f"(c0[j]), "+f"(c1[j]), "+f"(c2[j]), "+f"(c3[j])
                    : "r"(a0l), "r"(a1l), "r"(a2l), "r"(a3l), "r"(b0h), "r"(b1h));
            }
        }
        __syncthreads();
    }

    int row0 = bm + mw + g;
    int row1 = row0 + 8;
    float v0[5], w0[5], v1[5], w1[5];
#pragma unroll
    for (int j = 0; j < 5; j++) {
        float2 b = *(const float2*)(b5 + j * 8 + t2);
        v0[j] = c0[j] * 0.125f + b.x;
        w0[j] = c1[j] * 0.125f + b.y;
        v1[j] = c2[j] * 0.125f + b.x;
        w1[j] = c3[j] * 0.125f + b.y;
    }
    float m0 = -1e30f, m1 = -1e30f;
#pragma unroll
    for (int j = 0; j < 5; j++) {
        m0 = fmaxf(m0, fmaxf(v0[j], w0[j]));
        m1 = fmaxf(m1, fmaxf(v1[j], w1[j]));
    }
    m0 = fmaxf(m0, __shfl_xor_sync(0xffffffffu, m0, 1));
    m0 = fmaxf(m0, __shfl_xor_sync(0xffffffffu, m0, 2));
    m1 = fmaxf(m1, __shfl_xor_sync(0xffffffffu, m1, 1));
    m1 = fmaxf(m1, __shfl_xor_sync(0xffffffffu, m1, 2));
    float s0 = 0.f, s1 = 0.f;
#pragma unroll
    for (int j = 0; j < 5; j++) {
        s0 += __expf(v0[j] - m0) + __expf(w0[j] - m0);
        s1 += __expf(v1[j] - m1) + __expf(w1[j] - m1);
    }
    s0 += __shfl_xor_sync(0xffffffffu, s0, 1);
    s0 += __shfl_xor_sync(0xffffffffu, s0, 2);
    s1 += __shfl_xor_sync(0xffffffffu, s1, 1);
    s1 += __shfl_xor_sync(0xffffffffu, s1, 2);
    float lse0 = m0 + __logf(s0);
    float lse1 = m1 + __logf(s1);

    if (row0 < n) {
#pragma unroll
        for (int j = 0; j < 5; j++)
            *(float2*)(out + (size_t)row0 * 40 + j * 8 + t2) =
                make_float2(v0[j] - lse0, w0[j] - lse0);
    }
    if (row1 < n) {
#pragma unroll
        for (int j = 0; j < 5; j++)
            *(float2*)(out + (size_t)row1 * 40 + j * 8 + t2) =
                make_float2(v1[j] - lse1, w1[j] - lse1);
    }
}

// ---------------- host ----------------
static void* sym(const void* s) {
    void* p = nullptr;
    cudaGetSymbolAddress(&p, s);
    return p;
}

extern "C" void kernel_launch(void* const* d_in, const int* in_sizes, int n_in,
                              void* d_out, int out_size)
{
    const float* x   = (const float*)d_in[0];
    const int*   ei  = (const int*)d_in[1];
    const float* Ws[5]  = {(const float*)d_in[2],  (const float*)d_in[6],
                           (const float*)d_in[10], (const float*)d_in[14],
                           (const float*)d_in[18]};
    const float* asv[5] = {(const float*)d_in[3],  (const float*)d_in[7],
                           (const float*)d_in[11], (const float*)d_in[15],
                           (const float*)d_in[19]};
    const float* adv[5] = {(const float*)d_in[4],  (const float*)d_in[8],
                           (const float*)d_in[12], (const float*)d_in[16],
                           (const float*)d_in[20]};
    const float* bs[5]  = {(const float*)d_in[5],  (const float*)d_in[9],
                           (const float*)d_in[13], (const float*)d_in[17],
                           (const float*)d_in[21]};

    int n = in_sizes[0] / 128;
    int E = in_sizes[1] / 2;

    float* hs     = (float*)sym(g_hs);
    float* act    = (float*)sym(g_act);
    float* sbuf   = (float*)sym(g_sbuf);
    float* exbuf  = (float*)sym(g_ex);
    int*   col    = (int*)  sym(g_col);
    int*   rowptr = (int*)  sym(g_rowptr);
    int*   cursor = (int*)  sym(g_cursor);
    int*   cnt    = (int*)  sym(g_cnt);
    int*   bsum   = (int*)  sym(g_bsum);
    __nv_bfloat16* xh  = (__nv_bfloat16*)sym(g_xh);
    __nv_bfloat16* xl  = (__nv_bfloat16*)sym(g_xl);
    __nv_bfloat16* ah  = (__nv_bfloat16*)sym(g_ah);
    __nv_bfloat16* al  = (__nv_bfloat16*)sym(g_al);
    __nv_bfloat16* yh  = (__nv_bfloat16*)sym(g_yh);
    __nv_bfloat16* yl  = (__nv_bfloat16*)sym(g_yl);
    __nv_bfloat16* Wth = (__nv_bfloat16*)sym(g_Wth);
    __nv_bfloat16* Wtl = (__nv_bfloat16*)sym(g_Wtl);
    __nv_bfloat16* Bth = (__nv_bfloat16*)sym(g_Bth);
    __nv_bfloat16* Btl = (__nv_bfloat16*)sym(g_Btl);
    float* Wfold  = (float*)sym(g_Wfold);

    // ---- CSR build (dst-grouped) ----
    int nb = (n + 1023) / 1024;
    k_init_cnt<<<(n + 255) / 256, 256>>>(cnt, n);
    k_hist<<<(E + 255) / 256, 256>>>(ei + E, cnt, E);
    k_scan1<<<nb, 1024>>>(cnt, rowptr, bsum, n);
    k_scan2<<<1, 64>>>(bsum, nb);
    k_scan3<<<(n + 255) / 256, 256>>>(rowptr, cursor, bsum, cnt, n);
    k_scatter<<<(E + n + 255) / 256, 256>>>(ei, cursor, col, E, n);

    int warpBlocks = (n + 7) / 8;
    int rowGrid = (n + 127) / 128;
    int tcGrid  = (n + 63) / 64;

    // ---- split x into bf16 planes (overlaps with CSR build workload) ----
    k_split<<<(n * 128 + 255) / 256, 256>>>(x, xh, xl, n * 128);

    // ---- layers 1..4: tensor-core fused [h|s] GEMM + one-pass aggregate ----
    for (int L = 0; L < 4; L++) {
        int K = (L == 0) ? 128 : 64;
        k_prep_bcat_t<<<(80 * K + 255) / 256, 256>>>(Ws[L], asv[L], adv[L], Bth, Btl, K);
        k_gemm80_tc<<<tcGrid, 128>>>((L == 0) ? xh : ah, (L == 0) ? xl : al,
                                     Bth, Btl, hs, n, K);
        k_agg_cat<<<warpBlocks, 256>>>(hs, rowptr, col, bs[L], ah, al,
                                       (L == 3) ? act : nullptr, n);
    }

    // ---- layer 5 ----
    k_fold<<<(64 * 16 + 255) / 256, 256>>>(Ws[4], asv[4], adv[4], Wfold, 64, 40);
    {
        dim3 g(1, rowGrid);
        k_gemm<1><<<g, 256>>>(act, Wfold, sbuf, n, 16, 64);
    }
    k_agg_mean<<<warpBlocks, 256>>>(act, sbuf, rowptr, col, yh, yl, exbuf, n);
    k_wprep<<<(40 * 512 + 255) / 256, 256>>>(Ws[4], Wth, Wtl);
    k_gemm_tc<<<tcGrid, 128>>>(yh, yl, Wth, Wtl, bs[4], (float*)d_out, n);
}